// round 11
// baseline (speedup 1.0000x reference)
#include <cuda_runtime.h>
#include <cstdint>

#define IGNORE_INDEX (-100)
static constexpr int B_ = 4, S_ = 2048, D_ = 2048, V_ = 32000;
static constexpr int NROWS  = B_ * (S_ - 1);   // 8188
static constexpr int MPAD   = 8192;
static constexpr int MTILES = MPAD / 128;      // 64
static constexpr int NT     = 128;             // CTA N tile / v-chunk
static constexpr int VCHUNKS = V_ / NT;        // 250
static constexpr int KC     = 128;             // K (int8) per stage
static constexpr int KITERS = D_ / KC;         // 16
static constexpr int A_BYTES = 128 * KC;       // 16384
static constexpr int B_BYTES = NT * KC;        // 16384
static constexpr int STAGE_BYTES = A_BYTES + B_BYTES;   // 32768
static constexpr int NSTAGE = 3;
// [0..48) mbarriers (3 full + 3 empty), [1024..2048) red-max, [2048..3072) red-sum
static constexpr int O_RED  = 1024;
static constexpr int O_STAGE = 3072;
static constexpr int SMEM_REQ = 1023 + O_STAGE + NSTAGE * STAGE_BYTES;  // 102399

__device__ __align__(1024) int8_t g_h8[(size_t)MPAD * D_];   // tiled+swizzled
__device__ __align__(1024) int8_t g_w8[(size_t)V_ * D_];     // tiled+swizzled
__device__ float g_sh[MPAD];
__device__ float g_sw[V_];
__device__ float g_pmax[(size_t)VCHUNKS * MPAD];
__device__ float g_psum[(size_t)VCHUNKS * MPAD];
__device__ float g_gold[MPAD];
__device__ float g_bsum[32];
__device__ float g_bcnt[32];

__device__ __forceinline__ uint32_t smem_u32(const void* p) {
    uint32_t a;
    asm("{ .reg .u64 t; cvta.to.shared.u64 t, %1; cvt.u32.u64 %0, t; }" : "=r"(a) : "l"(p));
    return a;
}
#define MBAR_INIT(a, c) \
    asm volatile("mbarrier.init.shared.b64 [%0], %1;" :: "r"(a), "r"(c) : "memory")
#define MBAR_EXPECT_TX(a, b) \
    asm volatile("mbarrier.arrive.expect_tx.shared.b64 _, [%0], %1;" :: "r"(a), "r"(b) : "memory")
#define MBAR_ARRIVE(a) \
    asm volatile("mbarrier.arrive.shared.b64 _, [%0];" :: "r"(a) : "memory")
#define MBAR_WAIT(mbar, ph) do {                                                        \
    uint32_t _m = (uint32_t)(mbar); uint32_t _p = (uint32_t)(ph); uint32_t _d;          \
    asm volatile("{\n\t.reg .pred p;\n\t"                                               \
        "mbarrier.try_wait.parity.acquire.cta.shared::cta.b64 p, [%1], %2;\n\t"         \
        "selp.b32 %0, 1, 0, p;\n\t}" : "=r"(_d) : "r"(_m), "r"(_p) : "memory");         \
    if (!_d) {                                                                          \
        asm volatile("{\n\t.reg .pred P1;\n"                                            \
            "WAIT_LOOP_%=:\n\t"                                                         \
            "mbarrier.try_wait.parity.acquire.cta.shared::cta.b64 P1, [%0], %1, 0x989680;\n\t" \
            "@P1 bra.uni WAIT_DONE_%=;\n\t"                                             \
            "bra.uni WAIT_LOOP_%=;\n"                                                   \
            "WAIT_DONE_%=:\n\t}" :: "r"(_m), "r"(_p) : "memory");                       \
    }                                                                                   \
} while (0)
#define BULK_G2S(dst, src, bytes, mbar)                                                 \
    asm volatile("cp.async.bulk.shared::cluster.global.mbarrier::complete_tx::bytes "   \
                 "[%0], [%1], %2, [%3];"                                                \
                 :: "r"(dst), "l"(src), "r"(bytes), "r"(mbar) : "memory")
#define FENCE_PROXY() asm volatile("fence.proxy.async.shared::cta;" ::: "memory")

#define LDSM_X4(r0, r1, r2, r3, addr) \
    asm volatile("ldmatrix.sync.aligned.m8n8.x4.shared.b16 {%0,%1,%2,%3}, [%4];" \
        : "=r"(r0), "=r"(r1), "=r"(r2), "=r"(r3) : "r"(addr))

// int8 MMA: M16 N8 K32, s32 accum. A/B fragment byte layout matches
// ldmatrix.b16.x4 output on 32-byte K-major rows exactly like the f16 case.
#define MMA16832(d, a0, a1, a2, a3, b0, b1) \
    asm volatile("mma.sync.aligned.m16n8k32.row.col.s32.s8.s8.s32 " \
        "{%0,%1,%2,%3}, {%4,%5,%6,%7}, {%8,%9}, {%0,%1,%2,%3};" \
        : "+r"((d)[0]), "+r"((d)[1]), "+r"((d)[2]), "+r"((d)[3]) \
        : "r"(a0), "r"(a1), "r"(a2), "r"(a3), "r"(b0), "r"(b1))

__device__ __forceinline__ uint32_t swz128(uint32_t b) { return b ^ ((b >> 3) & 0x70); }

// ---- quantize one row of D_ floats to int8 with per-row symmetric scale ----
// warp per row; lane loads 16 float4 at 512B stride (fully coalesced).
__device__ __forceinline__ void quant_row(const float* __restrict__ src, bool valid,
                                          int n, int8_t* __restrict__ dst_base,
                                          float* __restrict__ scale_out, int l) {
    float4 v[16];
    float m = 0.f;
    #pragma unroll
    for (int i = 0; i < 16; ++i) {
        if (valid) v[i] = *reinterpret_cast<const float4*>(src + l * 4 + i * 128);
        else       v[i] = make_float4(0.f, 0.f, 0.f, 0.f);
        m = fmaxf(m, fmaxf(fmaxf(fabsf(v[i].x), fabsf(v[i].y)),
                           fmaxf(fabsf(v[i].z), fabsf(v[i].w))));
    }
    #pragma unroll
    for (int o = 16; o; o >>= 1) m = fmaxf(m, __shfl_xor_sync(0xffffffffu, m, o));
    const float inv = (m > 0.f) ? 127.f / m : 0.f;
    if (l == 0) scale_out[n] = (m > 0.f) ? m * (1.f / 127.f) : 1.f;
    #pragma unroll
    for (int i = 0; i < 16; ++i) {
        int d = l * 4 + i * 128;
        int q0 = __float2int_rn(v[i].x * inv), q1 = __float2int_rn(v[i].y * inv);
        int q2 = __float2int_rn(v[i].z * inv), q3 = __float2int_rn(v[i].w * inv);
        uint32_t packed = (uint32_t)(q0 & 0xff) | ((uint32_t)(q1 & 0xff) << 8) |
                          ((uint32_t)(q2 & 0xff) << 16) | ((uint32_t)(q3 & 0xff) << 24);
        int kit = d >> 7, c = d & 127;
        size_t tile = ((size_t)((n >> 7) * KITERS + kit)) << 14;   // 16KB tiles
        uint32_t byte = (uint32_t)(n & 127) * 128u + (uint32_t)c;
        *reinterpret_cast<uint32_t*>(dst_base + tile + swz128(byte)) = packed;
    }
}

__global__ void k_convert_h(const float* __restrict__ hs) {
    int n = (int)(((size_t)blockIdx.x * blockDim.x + threadIdx.x) >> 5);
    int l = threadIdx.x & 31;
    if (n >= MPAD) return;
    const float* src = nullptr;
    bool valid = n < NROWS;
    if (valid) {
        int b = n / (S_ - 1), s = n % (S_ - 1);
        src = hs + (size_t)(b * S_ + s) * D_;
    }
    quant_row(src, valid, n, g_h8, g_sh, l);
}
__global__ void k_convert_w(const float* __restrict__ w) {
    int n = (int)(((size_t)blockIdx.x * blockDim.x + threadIdx.x) >> 5);
    int l = threadIdx.x & 31;
    if (n >= V_) return;
    quant_row(w + (size_t)n * D_, true, n, g_w8, g_sw, l);
}

// ---- fused int8 GEMM (mma.sync m16n8k32) + partial logsumexp per 128-col chunk ----
// 256 threads, 2 CTAs/SM, mbarrier producer-consumer pipeline with deferred
// rotating-producer refill (see R9). Dequant (sh[m]*sw[v]) in epilogue.
__global__ void __launch_bounds__(256, 2) k_gemm_lse() {
    extern __shared__ char smem_raw[];
    const uint32_t raw = smem_u32(smem_raw);
    const uint32_t sb = (raw + 1023u) & ~1023u;
    const uint32_t pad = sb - raw;
    float* s_redm = reinterpret_cast<float*>(smem_raw + pad + O_RED);         // [128][2]
    float* s_reds = reinterpret_cast<float*>(smem_raw + pad + O_RED + 1024);  // [128][2]
    const uint32_t o_full  = sb;        // 3 mbarriers (tx-based fills)
    const uint32_t o_empty = sb + 24;   // 3 mbarriers (count=256 consumer arrivals)
    const uint32_t o_stage = sb + O_STAGE;

    const int tid = threadIdx.x;
    const int wid = tid >> 5, l = tid & 31;
    const int mw = wid & 3, nw = wid >> 2;          // 4 M-warps x 2 N-warps
    const int wm = mw * 32, wn = nw * 64;

    if (tid == 0) {
        MBAR_INIT(o_full + 0, 1);   MBAR_INIT(o_full + 8, 1);   MBAR_INIT(o_full + 16, 1);
        MBAR_INIT(o_empty + 0, 256); MBAR_INIT(o_empty + 8, 256); MBAR_INIT(o_empty + 16, 256);
        FENCE_PROXY();
    }
    __syncthreads();

    const int mt = blockIdx.x, vc = blockIdx.y;
    const int8_t* ha = g_h8 + (size_t)mt * ((size_t)KITERS * A_BYTES);
    const int8_t* wb = g_w8 + (size_t)vc * ((size_t)KITERS * B_BYTES);

    if (tid == 0) {
        #pragma unroll
        for (int p = 0; p < NSTAGE; ++p) {
            MBAR_EXPECT_TX(o_full + 8 * p, STAGE_BYTES);
            BULK_G2S(o_stage + p * STAGE_BYTES,           ha + (size_t)p * A_BYTES, A_BYTES, o_full + 8 * p);
            BULK_G2S(o_stage + p * STAGE_BYTES + A_BYTES, wb + (size_t)p * B_BYTES, B_BYTES, o_full + 8 * p);
        }
    }

    // per-lane ldmatrix address components (swizzle mask depends only on row%8)
    const uint32_t a_row = (uint32_t)(wm + (l & 15));
    const uint32_t a_base = a_row * 128u;
    const uint32_t a_mask = (a_row & 7u) << 4;
    const uint32_t a_cb = (uint32_t)((l >> 4) * 16);
    const uint32_t b_row = (uint32_t)(wn + (l & 7) + ((l >> 4) << 3));
    const uint32_t b_base = b_row * 128u;
    const uint32_t b_mask = (b_row & 7u) << 4;
    const uint32_t b_cb = (uint32_t)(((l >> 3) & 1) * 16);

    int acc[2][8][4];
    #pragma unroll
    for (int i = 0; i < 2; ++i)
        #pragma unroll
        for (int j = 0; j < 8; ++j)
            #pragma unroll
            for (int q = 0; q < 4; ++q) acc[i][j][q] = 0;

    int s = 0, ph = 0;
    for (int it = 0; it < KITERS; ++it) {
        // Deferred refill of the stage freed at it-1; producer rotates (warp it&7).
        if (it >= 1 && it - 1 + NSTAGE < KITERS && tid == ((it & 7) << 5)) {
            const int sp = (it - 1) % NSTAGE;
            const uint32_t pA = o_stage + sp * STAGE_BYTES;
            MBAR_WAIT(o_empty + 8 * sp, ((it - 1) / NSTAGE) & 1);
            MBAR_EXPECT_TX(o_full + 8 * sp, STAGE_BYTES);
            BULK_G2S(pA,           ha + (size_t)(it - 1 + NSTAGE) * A_BYTES, A_BYTES, o_full + 8 * sp);
            BULK_G2S(pA + A_BYTES, wb + (size_t)(it - 1 + NSTAGE) * B_BYTES, B_BYTES, o_full + 8 * sp);
        }
        MBAR_WAIT(o_full + 8 * s, ph);
        const uint32_t stA = o_stage + s * STAGE_BYTES;
        const uint32_t stB = stA + A_BYTES;
        #pragma unroll
        for (int kk = 0; kk < 4; ++kk) {    // 4 x K=32 int8 per 128B stage row
            uint32_t a0[4], a1[4], b[4][4];
            const uint32_t aAdr = stA + a_base + ((a_cb + kk * 32u) ^ a_mask);
            LDSM_X4(a0[0], a0[1], a0[2], a0[3], aAdr);
            LDSM_X4(a1[0], a1[1], a1[2], a1[3], aAdr + 2048u);
            const uint32_t bAdr = stB + b_base + ((b_cb + kk * 32u) ^ b_mask);
            #pragma unroll
            for (int j = 0; j < 4; ++j)
                LDSM_X4(b[j][0], b[j][1], b[j][2], b[j][3], bAdr + (uint32_t)j * 2048u);
            #pragma unroll
            for (int j = 0; j < 4; ++j) {
                MMA16832(acc[0][2 * j],     a0[0], a0[1], a0[2], a0[3], b[j][0], b[j][1]);
                MMA16832(acc[1][2 * j],     a1[0], a1[1], a1[2], a1[3], b[j][0], b[j][1]);
                MMA16832(acc[0][2 * j + 1], a0[0], a0[1], a0[2], a0[3], b[j][2], b[j][3]);
                MMA16832(acc[1][2 * j + 1], a1[0], a1[1], a1[2], a1[3], b[j][2], b[j][3]);
            }
        }
        MBAR_ARRIVE(o_empty + 8 * s);   // release: my reads of stage s done
        if (++s == NSTAGE) { s = 0; ph ^= 1; }
    }

    // ---- dequant in place: logit = acc * sh[row] * sw[col] ----
    // frag: q=2h+c -> row-half h (d0,d1 vs d2,d3), col c; rows wm+(mti*2+h mapping below)
    float sh[4];
    #pragma unroll
    for (int sl = 0; sl < 4; ++sl) {
        int row = wm + (sl >> 1) * 16 + (sl & 1) * 8 + (l >> 2);
        sh[sl] = g_sh[mt * 128 + row];
    }
    float swc[16];
    #pragma unroll
    for (int jj = 0; jj < 8; ++jj)
        #pragma unroll
        for (int c = 0; c < 2; ++c) {
            int coln = wn + (jj >> 1) * 16 + (jj & 1) * 8 + (l & 3) * 2 + c;
            swc[jj * 2 + c] = g_sw[(size_t)vc * NT + coln];
        }
    #pragma unroll
    for (int i = 0; i < 2; ++i)
        #pragma unroll
        for (int j = 0; j < 8; ++j)
            #pragma unroll
            for (int q = 0; q < 4; ++q)
                acc[i][j][q] = __float_as_int(
                    (float)acc[i][j][q] * sh[i * 2 + (q >> 1)] * swc[j * 2 + (q & 1)]);

    // ---- epilogue: per-row max & sum(exp) over this CTA's 128 columns ----
    float mx[4];
    #pragma unroll
    for (int mti = 0; mti < 2; ++mti)
        #pragma unroll
        for (int h = 0; h < 2; ++h) {
            float m = -1e30f;
            #pragma unroll
            for (int j = 0; j < 8; ++j)
                m = fmaxf(m, fmaxf(__int_as_float(acc[mti][j][2 * h]),
                                   __int_as_float(acc[mti][j][2 * h + 1])));
            m = fmaxf(m, __shfl_xor_sync(0xffffffffu, m, 1));
            m = fmaxf(m, __shfl_xor_sync(0xffffffffu, m, 2));
            mx[mti * 2 + h] = m;
        }
    if ((l & 3) == 0) {
        #pragma unroll
        for (int sl = 0; sl < 4; ++sl) {
            int row = wm + (sl >> 1) * 16 + (sl & 1) * 8 + (l >> 2);
            s_redm[row * 2 + nw] = mx[sl];
        }
    }
    __syncthreads();
    float fm[4], sm[4];
    #pragma unroll
    for (int sl = 0; sl < 4; ++sl) {
        int row = wm + (sl >> 1) * 16 + (sl & 1) * 8 + (l >> 2);
        float m = fmaxf(s_redm[row * 2 + 0], s_redm[row * 2 + 1]);
        fm[sl] = m;
        int mti = sl >> 1, h = sl & 1;
        float ss = 0.f;
        #pragma unroll
        for (int j = 0; j < 8; ++j)
            ss += __expf(__int_as_float(acc[mti][j][2 * h]) - m) +
                  __expf(__int_as_float(acc[mti][j][2 * h + 1]) - m);
        ss += __shfl_xor_sync(0xffffffffu, ss, 1);
        ss += __shfl_xor_sync(0xffffffffu, ss, 2);
        sm[sl] = ss;
    }
    if ((l & 3) == 0) {
        #pragma unroll
        for (int sl = 0; sl < 4; ++sl) {
            int row = wm + (sl >> 1) * 16 + (sl & 1) * 8 + (l >> 2);
            s_reds[row * 2 + nw] = sm[sl];
        }
    }
    __syncthreads();
    if (nw == 0 && (l & 3) == 0) {
        #pragma unroll
        for (int sl = 0; sl < 4; ++sl) {
            int row = wm + (sl >> 1) * 16 + (sl & 1) * 8 + (l >> 2);
            float tot = s_reds[row * 2 + 0] + s_reds[row * 2 + 1];
            size_t g = (size_t)vc * MPAD + (size_t)mt * 128 + row;
            g_pmax[g] = fm[sl];
            g_psum[g] = tot;
        }
    }
}

// ---- exact fp32 gold logit, one warp per row ----
__global__ void k_gold(const float* __restrict__ hs, const float* __restrict__ w,
                       const long long* __restrict__ labels) {
    int wg = (int)(((size_t)blockIdx.x * blockDim.x + threadIdx.x) >> 5);
    int lane = threadIdx.x & 31;
    if (wg >= NROWS) return;
    int b = wg / (S_ - 1), s = wg % (S_ - 1);
    long long t = labels[b * S_ + s + 1];
    float acc = 0.f;
    if (t != IGNORE_INDEX && t >= 0 && t < V_) {
        const float* hp = hs + (size_t)(b * S_ + s) * D_;
        const float* wp = w + (size_t)t * D_;
        for (int d = lane; d < D_; d += 32) acc += hp[d] * wp[d];
    }
    #pragma unroll
    for (int o = 16; o; o >>= 1) acc += __shfl_xor_sync(0xffffffffu, acc, o);
    if (lane == 0) g_gold[wg] = acc;
}

// ---- combine split-lse partials; deterministic block sums ----
__global__ void k_reduce1(const long long* __restrict__ labels) {
    __shared__ float s_nll[256], s_cnt[256];
    int row = blockIdx.x * 256 + threadIdx.x;
    float nll = 0.f, cnt = 0.f;
    if (row < NROWS) {
        int b = row / (S_ - 1), s = row % (S_ - 1);
        long long t = labels[b * S_ + s + 1];
        if (t != IGNORE_INDEX) {
            float m = -1e30f;
            for (int c = 0; c < VCHUNKS; ++c)
                m = fmaxf(m, g_pmax[(size_t)c * MPAD + row]);
            float ss = 0.f;
            for (int c = 0; c < VCHUNKS; ++c)
                ss += g_psum[(size_t)c * MPAD + row] *
                      __expf(g_pmax[(size_t)c * MPAD + row] - m);
            nll = m + logf(ss) - g_gold[row];
            cnt = 1.f;
        }
    }
    s_nll[threadIdx.x] = nll; s_cnt[threadIdx.x] = cnt;
    __syncthreads();
    for (int o = 128; o; o >>= 1) {
        if (threadIdx.x < o) {
            s_nll[threadIdx.x] += s_nll[threadIdx.x + o];
            s_cnt[threadIdx.x] += s_cnt[threadIdx.x + o];
        }
        __syncthreads();
    }
    if (threadIdx.x == 0) { g_bsum[blockIdx.x] = s_nll[0]; g_bcnt[blockIdx.x] = s_cnt[0]; }
}
__global__ void k_reduce2(float* __restrict__ out) {
    if (threadIdx.x == 0) {
        float s = 0.f, c = 0.f;
        for (int i = 0; i < 32; ++i) { s += g_bsum[i]; c += g_bcnt[i]; }
        out[0] = s / fmaxf(c, 1.f);
    }
}

extern "C" void kernel_launch(void* const* d_in, const int* in_sizes, int n_in,
                              void* d_out, int out_size) {
    const float* hs = (const float*)d_in[0];
    const float* w  = (const float*)d_in[1];
    const long long* labels = (const long long*)d_in[2];
    float* out = (float*)d_out;
    cudaFuncSetAttribute(k_gemm_lse, cudaFuncAttributeMaxDynamicSharedMemorySize, SMEM_REQ);
    k_convert_h<<<(MPAD * 32) / 256, 256>>>(hs);
    k_convert_w<<<(V_ * 32) / 256, 256>>>(w);
    k_gold<<<1024, 256>>>(hs, w, labels);
    dim3 grid(MTILES, VCHUNKS);
    k_gemm_lse<<<grid, 256, SMEM_REQ>>>();
    k_reduce1<<<32, 256>>>(labels);
    k_reduce2<<<1, 32>>>(out);
}

// round 12
// speedup vs baseline: 3.2997x; 3.2997x over previous
#include <cuda_runtime.h>
#include <cuda_fp16.h>
#include <cstdint>

#define IGNORE_INDEX (-100)
static constexpr int B_ = 4, S_ = 2048, D_ = 2048, V_ = 32000;
static constexpr int NROWS  = B_ * (S_ - 1);   // 8188
static constexpr int MPAD   = 8192;
static constexpr int MTILES = MPAD / 128;      // 64
static constexpr int NT     = 128;             // CTA N tile / v-chunk
static constexpr int VCHUNKS = V_ / NT;        // 250
static constexpr int NTILES_TOT = MTILES * VCHUNKS;  // 16000
static constexpr int KC     = 64;              // K per stage
static constexpr int KITERS = D_ / KC;         // 32
static constexpr int A_ELEMS = 128 * KC;       // 8192
static constexpr int B_ELEMS = NT * KC;        // 8192
static constexpr int A_BYTES = A_ELEMS * 2;    // 16384
static constexpr int B_BYTES = B_ELEMS * 2;    // 16384
static constexpr int STAGE_BYTES = A_BYTES + B_BYTES;   // 32768
static constexpr int NSTAGE = 3;
// [0..48) mbarriers (3 full + 3 empty), [1024..2048) red-max, [2048..3072) red-sum
static constexpr int O_RED  = 1024;
static constexpr int O_STAGE = 3072;
static constexpr int SMEM_REQ = 1023 + O_STAGE + NSTAGE * STAGE_BYTES;  // 102399

__device__ __align__(1024) __half g_h[(size_t)MPAD * D_];
__device__ __align__(1024) __half g_w[(size_t)V_ * D_];
__device__ float g_pmax[(size_t)VCHUNKS * MPAD];
__device__ float g_psum[(size_t)VCHUNKS * MPAD];
__device__ float g_gold[MPAD];
__device__ float g_bsum[32];
__device__ float g_bcnt[32];

__device__ __forceinline__ uint32_t smem_u32(const void* p) {
    uint32_t a;
    asm("{ .reg .u64 t; cvta.to.shared.u64 t, %1; cvt.u32.u64 %0, t; }" : "=r"(a) : "l"(p));
    return a;
}
#define MBAR_INIT(a, c) \
    asm volatile("mbarrier.init.shared.b64 [%0], %1;" :: "r"(a), "r"(c) : "memory")
#define MBAR_EXPECT_TX(a, b) \
    asm volatile("mbarrier.arrive.expect_tx.shared.b64 _, [%0], %1;" :: "r"(a), "r"(b) : "memory")
#define MBAR_ARRIVE(a) \
    asm volatile("mbarrier.arrive.shared.b64 _, [%0];" :: "r"(a) : "memory")
#define MBAR_WAIT(mbar, ph) do {                                                        \
    uint32_t _m = (uint32_t)(mbar); uint32_t _p = (uint32_t)(ph); uint32_t _d;          \
    asm volatile("{\n\t.reg .pred p;\n\t"                                               \
        "mbarrier.try_wait.parity.acquire.cta.shared::cta.b64 p, [%1], %2;\n\t"         \
        "selp.b32 %0, 1, 0, p;\n\t}" : "=r"(_d) : "r"(_m), "r"(_p) : "memory");         \
    if (!_d) {                                                                          \
        asm volatile("{\n\t.reg .pred P1;\n"                                            \
            "WAIT_LOOP_%=:\n\t"                                                         \
            "mbarrier.try_wait.parity.acquire.cta.shared::cta.b64 P1, [%0], %1, 0x989680;\n\t" \
            "@P1 bra.uni WAIT_DONE_%=;\n\t"                                             \
            "bra.uni WAIT_LOOP_%=;\n"                                                   \
            "WAIT_DONE_%=:\n\t}" :: "r"(_m), "r"(_p) : "memory");                       \
    }                                                                                   \
} while (0)
#define BULK_G2S(dst, src, bytes, mbar)                                                 \
    asm volatile("cp.async.bulk.shared::cluster.global.mbarrier::complete_tx::bytes "   \
                 "[%0], [%1], %2, [%3];"                                                \
                 :: "r"(dst), "l"(src), "r"(bytes), "r"(mbar) : "memory")
#define FENCE_PROXY() asm volatile("fence.proxy.async.shared::cta;" ::: "memory")

#define LDSM_X4(r0, r1, r2, r3, addr) \
    asm volatile("ldmatrix.sync.aligned.m8n8.x4.shared.b16 {%0,%1,%2,%3}, [%4];" \
        : "=r"(r0), "=r"(r1), "=r"(r2), "=r"(r3) : "r"(addr))

#define MMA16816(d, a0, a1, a2, a3, b0, b1) \
    asm volatile("mma.sync.aligned.m16n8k16.row.col.f32.f16.f16.f32 " \
        "{%0,%1,%2,%3}, {%4,%5,%6,%7}, {%8,%9}, {%0,%1,%2,%3};" \
        : "+f"((d)[0]), "+f"((d)[1]), "+f"((d)[2]), "+f"((d)[3]) \
        : "r"(a0), "r"(a1), "r"(a2), "r"(a3), "r"(b0), "r"(b1))

__device__ __forceinline__ uint32_t swz128(uint32_t b) { return b ^ ((b >> 3) & 0x70); }

// ---- pack shifted h -> tiled+swizzled fp16 (tile: 128 rows x 64 K = 16KB) ----
__global__ void k_convert_h(const float* __restrict__ hs) {
    size_t idx = (size_t)blockIdx.x * blockDim.x + threadIdx.x;   // quad index
    if (idx >= (size_t)MPAD * (D_ / 4)) return;
    int n = (int)(idx >> 9);
    int d = (int)(idx & 511) * 4;
    float4 v = make_float4(0.f, 0.f, 0.f, 0.f);
    if (n < NROWS) {
        int b = n / (S_ - 1), s = n % (S_ - 1);
        v = *reinterpret_cast<const float4*>(hs + ((size_t)(b * S_ + s) * D_ + d));
    }
    int kit = d >> 6, c = d & 63;
    size_t tile = ((size_t)((n >> 7) * KITERS + kit)) << 13;
    uint32_t byte = (uint32_t)(n & 127) * 128u + (uint32_t)c * 2u;
    __half2* p = reinterpret_cast<__half2*>(
        reinterpret_cast<char*>(g_h + tile) + swz128(byte));
    p[0] = __floats2half2_rn(v.x, v.y);
    p[1] = __floats2half2_rn(v.z, v.w);
}
// ---- pack W -> tiled+swizzled fp16 (tile: 128 rows x 64 K = 16KB) ----
__global__ void k_convert_w(const float* __restrict__ w) {
    size_t idx = (size_t)blockIdx.x * blockDim.x + threadIdx.x;   // quad index
    if (idx >= (size_t)V_ * (D_ / 4)) return;
    int v = (int)(idx >> 9);
    int d = (int)(idx & 511) * 4;
    float4 val = *reinterpret_cast<const float4*>(w + (size_t)v * D_ + d);
    int kit = d >> 6, c = d & 63;
    size_t tile = ((size_t)((v >> 7) * KITERS + kit)) << 13;
    uint32_t byte = (uint32_t)(v & 127) * 128u + (uint32_t)c * 2u;
    __half2* p = reinterpret_cast<__half2*>(
        reinterpret_cast<char*>(g_w + tile) + swz128(byte));
    p[0] = __floats2half2_rn(val.x, val.y);
    p[1] = __floats2half2_rn(val.z, val.w);
}

// ---- PERSISTENT fused GEMM (mma.sync fp16) + partial logsumexp ----
// grid = 2*smCount co-resident CTAs; CTA b handles tiles t = i*G + b so
// concurrent CTAs share vc (L2-resident W). The mbarrier ring + global chunk
// counter g run continuously across tiles: pipeline fill happens ONCE per CTA,
// next tile's TMA fills overlap the current tile's epilogue, no wave gaps.
__global__ void __launch_bounds__(256, 2) k_gemm_lse() {
    extern __shared__ char smem_raw[];
    const uint32_t raw = smem_u32(smem_raw);
    const uint32_t sb = (raw + 1023u) & ~1023u;
    const uint32_t pad = sb - raw;
    float* s_redm = reinterpret_cast<float*>(smem_raw + pad + O_RED);         // [128][2]
    float* s_reds = reinterpret_cast<float*>(smem_raw + pad + O_RED + 1024);  // [128][2]
    const uint32_t o_full  = sb;        // 3 mbarriers (tx-based fills)
    const uint32_t o_empty = sb + 24;   // 3 mbarriers (count=256 consumer arrivals)
    const uint32_t o_stage = sb + O_STAGE;

    const int tid = threadIdx.x;
    const int wid = tid >> 5, l = tid & 31;
    const int mw = wid & 3, nw = wid >> 2;          // 4 M-warps x 2 N-warps
    const int wm = mw * 32, wn = nw * 64;

    const int G = (int)gridDim.x, bid = (int)blockIdx.x;
    const int base = NTILES_TOT / G, rem = NTILES_TOT % G;
    const int ntile = base + (bid < rem ? 1 : 0);
    if (ntile == 0) return;
    const int nch = ntile * KITERS;

    if (tid == 0) {
        MBAR_INIT(o_full + 0, 1);   MBAR_INIT(o_full + 8, 1);   MBAR_INIT(o_full + 16, 1);
        MBAR_INIT(o_empty + 0, 256); MBAR_INIT(o_empty + 8, 256); MBAR_INIT(o_empty + 16, 256);
        FENCE_PROXY();
    }
    __syncthreads();

    // initial fills: chunks 0..2 (all within tile 0 since KITERS=32 >= 3)
    if (tid == 0) {
        const int t0 = bid;                       // tile for i=0
        const __half* ha = g_h + (size_t)(t0 & 63) * ((size_t)KITERS * A_ELEMS);
        const __half* wb = g_w + (size_t)(t0 >> 6) * ((size_t)KITERS * B_ELEMS);
        #pragma unroll
        for (int p = 0; p < NSTAGE; ++p) {
            MBAR_EXPECT_TX(o_full + 8 * p, STAGE_BYTES);
            BULK_G2S(o_stage + p * STAGE_BYTES,           ha + (size_t)p * A_ELEMS, A_BYTES, o_full + 8 * p);
            BULK_G2S(o_stage + p * STAGE_BYTES + A_BYTES, wb + (size_t)p * B_ELEMS, B_BYTES, o_full + 8 * p);
        }
    }

    // per-lane ldmatrix address components (swizzle mask depends only on row%8)
    const uint32_t a_row = (uint32_t)(wm + (l & 15));
    const uint32_t a_base = a_row * 128u;
    const uint32_t a_mask = (a_row & 7u) << 4;
    const uint32_t a_cb = (uint32_t)((l >> 4) * 16);
    const uint32_t b_row = (uint32_t)(wn + (l & 7) + ((l >> 4) << 3));
    const uint32_t b_base = b_row * 128u;
    const uint32_t b_mask = (b_row & 7u) << 4;
    const uint32_t b_cb = (uint32_t)(((l >> 3) & 1) * 16);

    float acc[2][8][4];
    #pragma unroll
    for (int i = 0; i < 2; ++i)
        #pragma unroll
        for (int j = 0; j < 8; ++j)
            #pragma unroll
            for (int q = 0; q < 4; ++q) acc[i][j][q] = 0.f;

    int s = 0, ph = 0, g = 0;
    for (int i = 0; i < ntile; ++i) {
        const int t = i * G + bid;
        const int mt = t & 63, vc = t >> 6;
        for (int it = 0; it < KITERS; ++it, ++g) {
            // Deferred rotating-producer refill: service chunk freed at g-1
            // with chunk g+2 (possibly in the NEXT tile). Producer = lane 0
            // of warp (g & 7).
            if (g >= 1 && tid == ((g & 7) << 5)) {
                const int c = g + 2;
                if (c < nch) {
                    const int j = c >> 5, k = c & 31;
                    const int tj = j * G + bid;
                    const __half* haj = g_h + (size_t)(tj & 63) * ((size_t)KITERS * A_ELEMS)
                                            + (size_t)k * A_ELEMS;
                    const __half* wbj = g_w + (size_t)(tj >> 6) * ((size_t)KITERS * B_ELEMS)
                                            + (size_t)k * B_ELEMS;
                    const int sp = (g - 1) % NSTAGE;
                    const uint32_t pA = o_stage + sp * STAGE_BYTES;
                    MBAR_WAIT(o_empty + 8 * sp, ((g - 1) / NSTAGE) & 1);
                    MBAR_EXPECT_TX(o_full + 8 * sp, STAGE_BYTES);
                    BULK_G2S(pA,           haj, A_BYTES, o_full + 8 * sp);
                    BULK_G2S(pA + A_BYTES, wbj, B_BYTES, o_full + 8 * sp);
                }
            }
            MBAR_WAIT(o_full + 8 * s, ph);
            const uint32_t stA = o_stage + s * STAGE_BYTES;
            const uint32_t stB = stA + A_BYTES;
            #pragma unroll
            for (int kk = 0; kk < 4; ++kk) {
                uint32_t a0[4], a1[4], b[4][4];
                const uint32_t aAdr = stA + a_base + ((a_cb + kk * 32u) ^ a_mask);
                LDSM_X4(a0[0], a0[1], a0[2], a0[3], aAdr);
                LDSM_X4(a1[0], a1[1], a1[2], a1[3], aAdr + 2048u);
                const uint32_t bAdr = stB + b_base + ((b_cb + kk * 32u) ^ b_mask);
                #pragma unroll
                for (int j = 0; j < 4; ++j)
                    LDSM_X4(b[j][0], b[j][1], b[j][2], b[j][3], bAdr + (uint32_t)j * 2048u);
                #pragma unroll
                for (int j = 0; j < 4; ++j) {
                    MMA16816(acc[0][2 * j],     a0[0], a0[1], a0[2], a0[3], b[j][0], b[j][1]);
                    MMA16816(acc[1][2 * j],     a1[0], a1[1], a1[2], a1[3], b[j][0], b[j][1]);
                    MMA16816(acc[0][2 * j + 1], a0[0], a0[1], a0[2], a0[3], b[j][2], b[j][3]);
                    MMA16816(acc[1][2 * j + 1], a1[0], a1[1], a1[2], a1[3], b[j][2], b[j][3]);
                }
            }
            MBAR_ARRIVE(o_empty + 8 * s);   // release: my reads of stage s done
            if (++s == NSTAGE) { s = 0; ph ^= 1; }
        }

        // ---- per-tile epilogue: row max & sum(exp) over 128 cols ----
        // (warp skew bounded by pipeline depth (3 chunks) << 32, so the smem
        //  red arrays cannot be touched by two tiles' epilogues concurrently)
        float mx[4];
        #pragma unroll
        for (int mti = 0; mti < 2; ++mti)
            #pragma unroll
            for (int h = 0; h < 2; ++h) {
                float m = -1e30f;
                #pragma unroll
                for (int j = 0; j < 8; ++j)
                    m = fmaxf(m, fmaxf(acc[mti][j][2 * h], acc[mti][j][2 * h + 1]));
                m = fmaxf(m, __shfl_xor_sync(0xffffffffu, m, 1));
                m = fmaxf(m, __shfl_xor_sync(0xffffffffu, m, 2));
                mx[mti * 2 + h] = m;
            }
        if ((l & 3) == 0) {
            #pragma unroll
            for (int sl = 0; sl < 4; ++sl) {
                int row = wm + (sl >> 1) * 16 + (sl & 1) * 8 + (l >> 2);
                s_redm[row * 2 + nw] = mx[sl];
            }
        }
        __syncthreads();
        float fm[4], sm[4];
        #pragma unroll
        for (int sl = 0; sl < 4; ++sl) {
            int row = wm + (sl >> 1) * 16 + (sl & 1) * 8 + (l >> 2);
            float m = fmaxf(s_redm[row * 2 + 0], s_redm[row * 2 + 1]);
            fm[sl] = m;
            int mti = sl >> 1, h = sl & 1;
            float ss = 0.f;
            #pragma unroll
            for (int j = 0; j < 8; ++j)
                ss += __expf(acc[mti][j][2 * h] - m) + __expf(acc[mti][j][2 * h + 1] - m);
            ss += __shfl_xor_sync(0xffffffffu, ss, 1);
            ss += __shfl_xor_sync(0xffffffffu, ss, 2);
            sm[sl] = ss;
        }
        if ((l & 3) == 0) {
            #pragma unroll
            for (int sl = 0; sl < 4; ++sl) {
                int row = wm + (sl >> 1) * 16 + (sl & 1) * 8 + (l >> 2);
                s_reds[row * 2 + nw] = sm[sl];
            }
        }
        __syncthreads();
        if (nw == 0 && (l & 3) == 0) {
            #pragma unroll
            for (int sl = 0; sl < 4; ++sl) {
                int row = wm + (sl >> 1) * 16 + (sl & 1) * 8 + (l >> 2);
                float tot = s_reds[row * 2 + 0] + s_reds[row * 2 + 1];
                size_t gg = (size_t)vc * MPAD + (size_t)mt * 128 + row;
                g_pmax[gg] = fm[sl];
                g_psum[gg] = tot;
            }
        }
        // reset accumulators for next tile
        #pragma unroll
        for (int ii = 0; ii < 2; ++ii)
            #pragma unroll
            for (int j = 0; j < 8; ++j)
                #pragma unroll
                for (int q = 0; q < 4; ++q) acc[ii][j][q] = 0.f;
    }
}

// ---- exact fp32 gold logit, one warp per row (float4-vectorized) ----
__global__ void k_gold(const float* __restrict__ hs, const float* __restrict__ w,
                       const long long* __restrict__ labels) {
    int wg = (int)(((size_t)blockIdx.x * blockDim.x + threadIdx.x) >> 5);
    int lane = threadIdx.x & 31;
    if (wg >= NROWS) return;
    int b = wg / (S_ - 1), s = wg % (S_ - 1);
    long long t = labels[b * S_ + s + 1];
    float acc = 0.f;
    if (t != IGNORE_INDEX && t >= 0 && t < V_) {
        const float* hp = hs + (size_t)(b * S_ + s) * D_;
        const float* wp = w + (size_t)t * D_;
        #pragma unroll
        for (int i = 0; i < D_ / 128; ++i) {
            int d = lane * 4 + i * 128;
            float4 hv = *reinterpret_cast<const float4*>(hp + d);
            float4 wv = *reinterpret_cast<const float4*>(wp + d);
            acc += hv.x * wv.x + hv.y * wv.y + hv.z * wv.z + hv.w * wv.w;
        }
    }
    #pragma unroll
    for (int o = 16; o; o >>= 1) acc += __shfl_xor_sync(0xffffffffu, acc, o);
    if (lane == 0) g_gold[wg] = acc;
}

// ---- combine split-lse partials; deterministic block sums ----
__global__ void k_reduce1(const long long* __restrict__ labels) {
    __shared__ float s_nll[256], s_cnt[256];
    int row = blockIdx.x * 256 + threadIdx.x;
    float nll = 0.f, cnt = 0.f;
    if (row < NROWS) {
        int b = row / (S_ - 1), s = row % (S_ - 1);
        long long t = labels[b * S_ + s + 1];
        if (t != IGNORE_INDEX) {
            float m = -1e30f;
            for (int c = 0; c < VCHUNKS; ++c)
                m = fmaxf(m, g_pmax[(size_t)c * MPAD + row]);
            float ss = 0.f;
            for (int c = 0; c < VCHUNKS; ++c)
                ss += g_psum[(size_t)c * MPAD + row] *
                      __expf(g_pmax[(size_t)c * MPAD + row] - m);
            nll = m + logf(ss) - g_gold[row];
            cnt = 1.f;
        }
    }
    s_nll[threadIdx.x] = nll; s_cnt[threadIdx.x] = cnt;
    __syncthreads();
    for (int o = 128; o; o >>= 1) {
        if (threadIdx.x < o) {
            s_nll[threadIdx.x] += s_nll[threadIdx.x + o];
            s_cnt[threadIdx.x] += s_cnt[threadIdx.x + o];
        }
        __syncthreads();
    }
    if (threadIdx.x == 0) { g_bsum[blockIdx.x] = s_nll[0]; g_bcnt[blockIdx.x] = s_cnt[0]; }
}
__global__ void k_reduce2(float* __restrict__ out) {
    if (threadIdx.x == 0) {
        float s = 0.f, c = 0.f;
        for (int i = 0; i < 32; ++i) { s += g_bsum[i]; c += g_bcnt[i]; }
        out[0] = s / fmaxf(c, 1.f);
    }
}

extern "C" void kernel_launch(void* const* d_in, const int* in_sizes, int n_in,
                              void* d_out, int out_size) {
    const float* hs = (const float*)d_in[0];
    const float* w  = (const float*)d_in[1];
    const long long* labels = (const long long*)d_in[2];
    float* out = (float*)d_out;
    cudaFuncSetAttribute(k_gemm_lse, cudaFuncAttributeMaxDynamicSharedMemorySize, SMEM_REQ);
    int dev = 0, smcount = 148;
    cudaGetDevice(&dev);
    cudaDeviceGetAttribute(&smcount, cudaDevAttrMultiProcessorCount, dev);
    k_convert_h<<<(MPAD * (D_ / 4)) / 256, 256>>>(hs);
    k_convert_w<<<(V_ * (D_ / 4)) / 256, 256>>>(w);
    k_gold<<<1024, 256>>>(hs, w, labels);
    k_gemm_lse<<<2 * smcount, 256, SMEM_REQ>>>();
    k_reduce1<<<32, 256>>>(labels);
    k_reduce2<<<1, 32>>>(out);
}

// round 13
// speedup vs baseline: 3.3864x; 1.0263x over previous
#include <cuda_runtime.h>
#include <cuda_fp16.h>
#include <cstdint>

#define IGNORE_INDEX (-100)
static constexpr int B_ = 4, S_ = 2048, D_ = 2048, V_ = 32000;
static constexpr int NROWS  = B_ * (S_ - 1);   // 8188
static constexpr int MPAD   = 8192;
static constexpr int MTILES = MPAD / 128;      // 64
static constexpr int NT     = 128;             // CTA N tile / v-chunk
static constexpr int VCHUNKS = V_ / NT;        // 250
static constexpr int KC     = 64;              // K per stage
static constexpr int KITERS = D_ / KC;         // 32
static constexpr int A_ELEMS = 128 * KC;       // 8192
static constexpr int B_ELEMS = NT * KC;        // 8192
static constexpr int A_BYTES = A_ELEMS * 2;    // 16384
static constexpr int B_BYTES = B_ELEMS * 2;    // 16384
static constexpr int STAGE_BYTES = A_BYTES + B_BYTES;   // 32768
static constexpr int NSTAGE = 3;
// [0..48) mbarriers (3 full + 3 empty), [1024..2048) red-max, [2048..3072) red-sum
static constexpr int O_RED  = 1024;
static constexpr int O_STAGE = 3072;
static constexpr int SMEM_REQ = 1023 + O_STAGE + NSTAGE * STAGE_BYTES;  // 102399

__device__ __align__(1024) __half g_h[(size_t)MPAD * D_];
__device__ __align__(1024) __half g_w[(size_t)V_ * D_];
__device__ int   g_lab[MPAD];
__device__ float g_pmax[(size_t)VCHUNKS * MPAD];
__device__ float g_psum[(size_t)VCHUNKS * MPAD];
__device__ float g_gold[MPAD];
__device__ float g_bsum[32];
__device__ float g_bcnt[32];

__device__ __forceinline__ uint32_t smem_u32(const void* p) {
    uint32_t a;
    asm("{ .reg .u64 t; cvta.to.shared.u64 t, %1; cvt.u32.u64 %0, t; }" : "=r"(a) : "l"(p));
    return a;
}
#define MBAR_INIT(a, c) \
    asm volatile("mbarrier.init.shared.b64 [%0], %1;" :: "r"(a), "r"(c) : "memory")
#define MBAR_EXPECT_TX(a, b) \
    asm volatile("mbarrier.arrive.expect_tx.shared.b64 _, [%0], %1;" :: "r"(a), "r"(b) : "memory")
#define MBAR_ARRIVE(a) \
    asm volatile("mbarrier.arrive.shared.b64 _, [%0];" :: "r"(a) : "memory")
#define MBAR_WAIT(mbar, ph) do {                                                        \
    uint32_t _m = (uint32_t)(mbar); uint32_t _p = (uint32_t)(ph); uint32_t _d;          \
    asm volatile("{\n\t.reg .pred p;\n\t"                                               \
        "mbarrier.try_wait.parity.acquire.cta.shared::cta.b64 p, [%1], %2;\n\t"         \
        "selp.b32 %0, 1, 0, p;\n\t}" : "=r"(_d) : "r"(_m), "r"(_p) : "memory");         \
    if (!_d) {                                                                          \
        asm volatile("{\n\t.reg .pred P1;\n"                                            \
            "WAIT_LOOP_%=:\n\t"                                                         \
            "mbarrier.try_wait.parity.acquire.cta.shared::cta.b64 P1, [%0], %1, 0x989680;\n\t" \
            "@P1 bra.uni WAIT_DONE_%=;\n\t"                                             \
            "bra.uni WAIT_LOOP_%=;\n"                                                   \
            "WAIT_DONE_%=:\n\t}" :: "r"(_m), "r"(_p) : "memory");                       \
    }                                                                                   \
} while (0)
#define BULK_G2S(dst, src, bytes, mbar)                                                 \
    asm volatile("cp.async.bulk.shared::cluster.global.mbarrier::complete_tx::bytes "   \
                 "[%0], [%1], %2, [%3];"                                                \
                 :: "r"(dst), "l"(src), "r"(bytes), "r"(mbar) : "memory")
#define FENCE_PROXY() asm volatile("fence.proxy.async.shared::cta;" ::: "memory")

#define LDSM_X4(r0, r1, r2, r3, addr) \
    asm volatile("ldmatrix.sync.aligned.m8n8.x4.shared.b16 {%0,%1,%2,%3}, [%4];" \
        : "=r"(r0), "=r"(r1), "=r"(r2), "=r"(r3) : "r"(addr))

#define MMA16816(d, a0, a1, a2, a3, b0, b1) \
    asm volatile("mma.sync.aligned.m16n8k16.row.col.f32.f16.f16.f32 " \
        "{%0,%1,%2,%3}, {%4,%5,%6,%7}, {%8,%9}, {%0,%1,%2,%3};" \
        : "+f"((d)[0]), "+f"((d)[1]), "+f"((d)[2]), "+f"((d)[3]) \
        : "r"(a0), "r"(a1), "r"(a2), "r"(a3), "r"(b0), "r"(b1))

__device__ __forceinline__ uint32_t swz128(uint32_t b) { return b ^ ((b >> 3) & 0x70); }

// ---- shifted labels: g_lab[n] = labels[b*S + s + 1] (else -1) ----
__global__ void k_lab(const long long* __restrict__ labels) {
    int n = blockIdx.x * blockDim.x + threadIdx.x;
    if (n >= MPAD) return;
    int v = -1;
    if (n < NROWS) {
        int b = n / (S_ - 1), s = n % (S_ - 1);
        long long t = labels[b * S_ + s + 1];
        v = (t != IGNORE_INDEX && t >= 0 && t < V_) ? (int)t : -1;
    }
    g_lab[n] = v;
}

// ---- pack shifted h -> tiled+swizzled fp16 (tile: 128 rows x 64 K = 16KB) ----
__global__ void k_convert_h(const float* __restrict__ hs) {
    size_t idx = (size_t)blockIdx.x * blockDim.x + threadIdx.x;   // quad index
    if (idx >= (size_t)MPAD * (D_ / 4)) return;
    int n = (int)(idx >> 9);
    int d = (int)(idx & 511) * 4;
    float4 v = make_float4(0.f, 0.f, 0.f, 0.f);
    if (n < NROWS) {
        int b = n / (S_ - 1), s = n % (S_ - 1);
        v = *reinterpret_cast<const float4*>(hs + ((size_t)(b * S_ + s) * D_ + d));
    }
    int kit = d >> 6, c = d & 63;
    size_t tile = ((size_t)((n >> 7) * KITERS + kit)) << 13;
    uint32_t byte = (uint32_t)(n & 127) * 128u + (uint32_t)c * 2u;
    __half2* p = reinterpret_cast<__half2*>(
        reinterpret_cast<char*>(g_h + tile) + swz128(byte));
    p[0] = __floats2half2_rn(v.x, v.y);
    p[1] = __floats2half2_rn(v.z, v.w);
}
// ---- pack W -> tiled+swizzled fp16 (tile: 128 rows x 64 K = 16KB) ----
__global__ void k_convert_w(const float* __restrict__ w) {
    size_t idx = (size_t)blockIdx.x * blockDim.x + threadIdx.x;   // quad index
    if (idx >= (size_t)V_ * (D_ / 4)) return;
    int v = (int)(idx >> 9);
    int d = (int)(idx & 511) * 4;
    float4 val = *reinterpret_cast<const float4*>(w + (size_t)v * D_ + d);
    int kit = d >> 6, c = d & 63;
    size_t tile = ((size_t)((v >> 7) * KITERS + kit)) << 13;
    uint32_t byte = (uint32_t)(v & 127) * 128u + (uint32_t)c * 2u;
    __half2* p = reinterpret_cast<__half2*>(
        reinterpret_cast<char*>(g_w + tile) + swz128(byte));
    p[0] = __floats2half2_rn(val.x, val.y);
    p[1] = __floats2half2_rn(val.z, val.w);
}

// ---- fused GEMM (mma.sync fp16) + partial logsumexp + gold extraction ----
// 256 threads, 2 CTAs/SM (R10 structure: best measured). No block-wide
// barriers in mainloop; deferred rotating-producer refill.
__global__ void __launch_bounds__(256, 2) k_gemm_lse() {
    extern __shared__ char smem_raw[];
    const uint32_t raw = smem_u32(smem_raw);
    const uint32_t sb = (raw + 1023u) & ~1023u;
    const uint32_t pad = sb - raw;
    float* s_redm = reinterpret_cast<float*>(smem_raw + pad + O_RED);         // [128][2]
    float* s_reds = reinterpret_cast<float*>(smem_raw + pad + O_RED + 1024);  // [128][2]
    const uint32_t o_full  = sb;        // 3 mbarriers (tx-based fills)
    const uint32_t o_empty = sb + 24;   // 3 mbarriers (count=256 consumer arrivals)
    const uint32_t o_stage = sb + O_STAGE;

    const int tid = threadIdx.x;
    const int wid = tid >> 5, l = tid & 31;
    const int mw = wid & 3, nw = wid >> 2;          // 4 M-warps x 2 N-warps
    const int wm = mw * 32, wn = nw * 64;

    if (tid == 0) {
        MBAR_INIT(o_full + 0, 1);   MBAR_INIT(o_full + 8, 1);   MBAR_INIT(o_full + 16, 1);
        MBAR_INIT(o_empty + 0, 256); MBAR_INIT(o_empty + 8, 256); MBAR_INIT(o_empty + 16, 256);
        FENCE_PROXY();
    }
    __syncthreads();

    const int mt = blockIdx.x, vc = blockIdx.y;
    const __half* ha = g_h + (size_t)mt * ((size_t)KITERS * A_ELEMS);
    const __half* wb = g_w + (size_t)vc * ((size_t)KITERS * B_ELEMS);

    if (tid == 0) {
        #pragma unroll
        for (int p = 0; p < NSTAGE; ++p) {
            MBAR_EXPECT_TX(o_full + 8 * p, STAGE_BYTES);
            BULK_G2S(o_stage + p * STAGE_BYTES,           ha + (size_t)p * A_ELEMS, A_BYTES, o_full + 8 * p);
            BULK_G2S(o_stage + p * STAGE_BYTES + A_BYTES, wb + (size_t)p * B_ELEMS, B_BYTES, o_full + 8 * p);
        }
    }

    // per-lane ldmatrix address components (swizzle mask depends only on row%8)
    const uint32_t a_row = (uint32_t)(wm + (l & 15));
    const uint32_t a_base = a_row * 128u;
    const uint32_t a_mask = (a_row & 7u) << 4;
    const uint32_t a_cb = (uint32_t)((l >> 4) * 16);
    const uint32_t b_row = (uint32_t)(wn + (l & 7) + ((l >> 4) << 3));
    const uint32_t b_base = b_row * 128u;
    const uint32_t b_mask = (b_row & 7u) << 4;
    const uint32_t b_cb = (uint32_t)(((l >> 3) & 1) * 16);

    float acc[2][8][4];
    #pragma unroll
    for (int i = 0; i < 2; ++i)
        #pragma unroll
        for (int j = 0; j < 8; ++j)
            #pragma unroll
            for (int q = 0; q < 4; ++q) acc[i][j][q] = 0.f;

    int s = 0, ph = 0;
    for (int it = 0; it < KITERS; ++it) {
        // Deferred refill: service the stage freed at iteration it-1.
        // Producer rotates: lane 0 of warp (it & 7).
        if (it >= 1 && it - 1 + NSTAGE < KITERS && tid == ((it & 7) << 5)) {
            const int sp = (it - 1) % NSTAGE;
            const uint32_t pA = o_stage + sp * STAGE_BYTES;
            MBAR_WAIT(o_empty + 8 * sp, ((it - 1) / NSTAGE) & 1);
            MBAR_EXPECT_TX(o_full + 8 * sp, STAGE_BYTES);
            BULK_G2S(pA,           ha + (size_t)(it - 1 + NSTAGE) * A_ELEMS, A_BYTES, o_full + 8 * sp);
            BULK_G2S(pA + A_BYTES, wb + (size_t)(it - 1 + NSTAGE) * B_ELEMS, B_BYTES, o_full + 8 * sp);
        }
        MBAR_WAIT(o_full + 8 * s, ph);
        const uint32_t stA = o_stage + s * STAGE_BYTES;
        const uint32_t stB = stA + A_BYTES;
        #pragma unroll
        for (int kk = 0; kk < 4; ++kk) {
            uint32_t a0[4], a1[4], b[4][4];
            const uint32_t aAdr = stA + a_base + ((a_cb + kk * 32u) ^ a_mask);
            LDSM_X4(a0[0], a0[1], a0[2], a0[3], aAdr);
            LDSM_X4(a1[0], a1[1], a1[2], a1[3], aAdr + 2048u);
            const uint32_t bAdr = stB + b_base + ((b_cb + kk * 32u) ^ b_mask);
            #pragma unroll
            for (int j = 0; j < 4; ++j)
                LDSM_X4(b[j][0], b[j][1], b[j][2], b[j][3], bAdr + (uint32_t)j * 2048u);
            #pragma unroll
            for (int j = 0; j < 4; ++j) {
                MMA16816(acc[0][2 * j],     a0[0], a0[1], a0[2], a0[3], b[j][0], b[j][1]);
                MMA16816(acc[1][2 * j],     a1[0], a1[1], a1[2], a1[3], b[j][0], b[j][1]);
                MMA16816(acc[0][2 * j + 1], a0[0], a0[1], a0[2], a0[3], b[j][2], b[j][3]);
                MMA16816(acc[1][2 * j + 1], a1[0], a1[1], a1[2], a1[3], b[j][2], b[j][3]);
            }
        }
        MBAR_ARRIVE(o_empty + 8 * s);   // release: my reads of stage s done
        if (++s == NSTAGE) { s = 0; ph ^= 1; }
    }

    // ---- gold extraction: if this tile's columns contain row's label, the
    //      owning thread writes the fp16-GEMM logit (consistent with lse) ----
    // frag col for acc[mti][j][2h+c]: wn + (j>>1)*16 + (j&1)*8 + (l&3)*2 + c
    // frag row for (sl = mti*2+h):    wm + (sl>>1)*16 + (sl&1)*8 + (l>>2)
    #pragma unroll
    for (int sl = 0; sl < 4; ++sl) {
        int row = wm + (sl >> 1) * 16 + (sl & 1) * 8 + (l >> 2);
        int t = g_lab[mt * 128 + row];
        int local = t - vc * NT - wn;
        if (local >= 0 && local < 64) {
            int mti = sl >> 1, h = sl & 1;
            #pragma unroll
            for (int j = 0; j < 8; ++j)
                #pragma unroll
                for (int c = 0; c < 2; ++c) {
                    int coln = (j >> 1) * 16 + (j & 1) * 8 + (l & 3) * 2 + c;
                    if (coln == local)
                        g_gold[mt * 128 + row] = acc[mti][j][2 * h + c];
                }
        }
    }

    // ---- epilogue: per-row max & sum(exp) over this CTA's 128 columns ----
    float mx[4];
    #pragma unroll
    for (int mti = 0; mti < 2; ++mti)
        #pragma unroll
        for (int h = 0; h < 2; ++h) {
            float m = -1e30f;
            #pragma unroll
            for (int j = 0; j < 8; ++j)
                m = fmaxf(m, fmaxf(acc[mti][j][2 * h], acc[mti][j][2 * h + 1]));
            m = fmaxf(m, __shfl_xor_sync(0xffffffffu, m, 1));
            m = fmaxf(m, __shfl_xor_sync(0xffffffffu, m, 2));
            mx[mti * 2 + h] = m;
        }
    if ((l & 3) == 0) {
        #pragma unroll
        for (int sl = 0; sl < 4; ++sl) {
            int row = wm + (sl >> 1) * 16 + (sl & 1) * 8 + (l >> 2);
            s_redm[row * 2 + nw] = mx[sl];
        }
    }
    __syncthreads();
    float fm[4], sm[4];
    #pragma unroll
    for (int sl = 0; sl < 4; ++sl) {
        int row = wm + (sl >> 1) * 16 + (sl & 1) * 8 + (l >> 2);
        float m = fmaxf(s_redm[row * 2 + 0], s_redm[row * 2 + 1]);
        fm[sl] = m;
        int mti = sl >> 1, h = sl & 1;
        float ss = 0.f;
        #pragma unroll
        for (int j = 0; j < 8; ++j)
            ss += __expf(acc[mti][j][2 * h] - m) + __expf(acc[mti][j][2 * h + 1] - m);
        ss += __shfl_xor_sync(0xffffffffu, ss, 1);
        ss += __shfl_xor_sync(0xffffffffu, ss, 2);
        sm[sl] = ss;
    }
    if ((l & 3) == 0) {
        #pragma unroll
        for (int sl = 0; sl < 4; ++sl) {
            int row = wm + (sl >> 1) * 16 + (sl & 1) * 8 + (l >> 2);
            s_reds[row * 2 + nw] = sm[sl];
        }
    }
    __syncthreads();
    if (nw == 0 && (l & 3) == 0) {
        #pragma unroll
        for (int sl = 0; sl < 4; ++sl) {
            int row = wm + (sl >> 1) * 16 + (sl & 1) * 8 + (l >> 2);
            float tot = s_reds[row * 2 + 0] + s_reds[row * 2 + 1];
            size_t g = (size_t)vc * MPAD + (size_t)mt * 128 + row;
            g_pmax[g] = fm[sl];
            g_psum[g] = tot;
        }
    }
}

// ---- combine split-lse partials; deterministic block sums ----
__global__ void k_reduce1() {
    __shared__ float s_nll[256], s_cnt[256];
    int row = blockIdx.x * 256 + threadIdx.x;
    float nll = 0.f, cnt = 0.f;
    if (row < NROWS) {
        int t = g_lab[row];
        if (t >= 0) {
            float m = -1e30f;
            for (int c = 0; c < VCHUNKS; ++c)
                m = fmaxf(m, g_pmax[(size_t)c * MPAD + row]);
            float ss = 0.f;
            for (int c = 0; c < VCHUNKS; ++c)
                ss += g_psum[(size_t)c * MPAD + row] *
                      __expf(g_pmax[(size_t)c * MPAD + row] - m);
            nll = m + logf(ss) - g_gold[row];
            cnt = 1.f;
        }
    }
    s_nll[threadIdx.x] = nll; s_cnt[threadIdx.x] = cnt;
    __syncthreads();
    for (int o = 128; o; o >>= 1) {
        if (threadIdx.x < o) {
            s_nll[threadIdx.x] += s_nll[threadIdx.x + o];
            s_cnt[threadIdx.x] += s_cnt[threadIdx.x + o];
        }
        __syncthreads();
    }
    if (threadIdx.x == 0) { g_bsum[blockIdx.x] = s_nll[0]; g_bcnt[blockIdx.x] = s_cnt[0]; }
}
__global__ void k_reduce2(float* __restrict__ out) {
    if (threadIdx.x == 0) {
        float s = 0.f, c = 0.f;
        for (int i = 0; i < 32; ++i) { s += g_bsum[i]; c += g_bcnt[i]; }
        out[0] = s / fmaxf(c, 1.f);
    }
}

extern "C" void kernel_launch(void* const* d_in, const int* in_sizes, int n_in,
                              void* d_out, int out_size) {
    const float* hs = (const float*)d_in[0];
    const float* w  = (const float*)d_in[1];
    const long long* labels = (const long long*)d_in[2];
    float* out = (float*)d_out;
    cudaFuncSetAttribute(k_gemm_lse, cudaFuncAttributeMaxDynamicSharedMemorySize, SMEM_REQ);
    k_lab<<<MPAD / 256, 256>>>(labels);
    k_convert_h<<<(MPAD * (D_ / 4)) / 256, 256>>>(hs);
    k_convert_w<<<(V_ * (D_ / 4)) / 256, 256>>>(w);
    dim3 grid(MTILES, VCHUNKS);
    k_gemm_lse<<<grid, 256, SMEM_REQ>>>();
    k_reduce1<<<32, 256>>>();
    k_reduce2<<<1, 32>>>(out);
}

// round 14
// speedup vs baseline: 3.3911x; 1.0014x over previous
#include <cuda_runtime.h>
#include <cuda_fp16.h>
#include <cstdint>

#define IGNORE_INDEX (-100)
static constexpr int B_ = 4, S_ = 2048, D_ = 2048, V_ = 32000;
static constexpr int NROWS  = B_ * (S_ - 1);   // 8188
static constexpr int MPAD   = 8192;
static constexpr int MTILES = MPAD / 128;      // 64
static constexpr int NT     = 128;             // CTA N tile / v-chunk
static constexpr int VCHUNKS = V_ / NT;        // 250
static constexpr int KC     = 64;              // K per stage
static constexpr int KITERS = D_ / KC;         // 32
static constexpr int A_ELEMS = 128 * KC;       // 8192
static constexpr int B_ELEMS = NT * KC;        // 8192
static constexpr int A_BYTES = A_ELEMS * 2;    // 16384
static constexpr int B_BYTES = B_ELEMS * 2;    // 16384
static constexpr int STAGE_BYTES = A_BYTES + B_BYTES;   // 32768
static constexpr int NSTAGE = 3;
// [0..48) mbarriers (3 full + 3 empty), [1024..2048) red-max, [2048..3072) red-sum
static constexpr int O_RED  = 1024;
static constexpr int O_STAGE = 3072;
static constexpr int SMEM_REQ = 1023 + O_STAGE + NSTAGE * STAGE_BYTES;  // 102399

// prep kernel grid sections
static constexpr int HQ_BLOCKS  = (MPAD * (D_ / 4)) / 256;   // 16384
static constexpr int WQ_BLOCKS  = (V_ * (D_ / 4)) / 256;     // 64000
static constexpr int LAB_BLOCKS = MPAD / 256;                // 32
static constexpr int PREP_BLOCKS = HQ_BLOCKS + WQ_BLOCKS + LAB_BLOCKS;

__device__ __align__(1024) __half g_h[(size_t)MPAD * D_];
__device__ __align__(1024) __half g_w[(size_t)V_ * D_];
__device__ int   g_lab[MPAD];
__device__ float g_pmax[(size_t)VCHUNKS * MPAD];
__device__ float g_psum[(size_t)VCHUNKS * MPAD];
__device__ float g_gold[MPAD];
__device__ float g_bsum[32];
__device__ float g_bcnt[32];
__device__ int   g_done;

__device__ __forceinline__ uint32_t smem_u32(const void* p) {
    uint32_t a;
    asm("{ .reg .u64 t; cvta.to.shared.u64 t, %1; cvt.u32.u64 %0, t; }" : "=r"(a) : "l"(p));
    return a;
}
#define MBAR_INIT(a, c) \
    asm volatile("mbarrier.init.shared.b64 [%0], %1;" :: "r"(a), "r"(c) : "memory")
#define MBAR_EXPECT_TX(a, b) \
    asm volatile("mbarrier.arrive.expect_tx.shared.b64 _, [%0], %1;" :: "r"(a), "r"(b) : "memory")
#define MBAR_ARRIVE(a) \
    asm volatile("mbarrier.arrive.shared.b64 _, [%0];" :: "r"(a) : "memory")
#define MBAR_WAIT(mbar, ph) do {                                                        \
    uint32_t _m = (uint32_t)(mbar); uint32_t _p = (uint32_t)(ph); uint32_t _d;          \
    asm volatile("{\n\t.reg .pred p;\n\t"                                               \
        "mbarrier.try_wait.parity.acquire.cta.shared::cta.b64 p, [%1], %2;\n\t"         \
        "selp.b32 %0, 1, 0, p;\n\t}" : "=r"(_d) : "r"(_m), "r"(_p) : "memory");         \
    if (!_d) {                                                                          \
        asm volatile("{\n\t.reg .pred P1;\n"                                            \
            "WAIT_LOOP_%=:\n\t"                                                         \
            "mbarrier.try_wait.parity.acquire.cta.shared::cta.b64 P1, [%0], %1, 0x989680;\n\t" \
            "@P1 bra.uni WAIT_DONE_%=;\n\t"                                             \
            "bra.uni WAIT_LOOP_%=;\n"                                                   \
            "WAIT_DONE_%=:\n\t}" :: "r"(_m), "r"(_p) : "memory");                       \
    }                                                                                   \
} while (0)
#define BULK_G2S(dst, src, bytes, mbar)                                                 \
    asm volatile("cp.async.bulk.shared::cluster.global.mbarrier::complete_tx::bytes "   \
                 "[%0], [%1], %2, [%3];"                                                \
                 :: "r"(dst), "l"(src), "r"(bytes), "r"(mbar) : "memory")
#define FENCE_PROXY() asm volatile("fence.proxy.async.shared::cta;" ::: "memory")

#define LDSM_X4(r0, r1, r2, r3, addr) \
    asm volatile("ldmatrix.sync.aligned.m8n8.x4.shared.b16 {%0,%1,%2,%3}, [%4];" \
        : "=r"(r0), "=r"(r1), "=r"(r2), "=r"(r3) : "r"(addr))

#define MMA16816(d, a0, a1, a2, a3, b0, b1) \
    asm volatile("mma.sync.aligned.m16n8k16.row.col.f32.f16.f16.f32 " \
        "{%0,%1,%2,%3}, {%4,%5,%6,%7}, {%8,%9}, {%0,%1,%2,%3};" \
        : "+f"((d)[0]), "+f"((d)[1]), "+f"((d)[2]), "+f"((d)[3]) \
        : "r"(a0), "r"(a1), "r"(a2), "r"(a3), "r"(b0), "r"(b1))

__device__ __forceinline__ uint32_t swz128(uint32_t b) { return b ^ ((b >> 3) & 0x70); }

// ---- fused prep: pack h (shifted) + pack W into tiled+swizzled fp16, and
//      build shifted labels + reset the reduce ticket. One launch. ----
__global__ void k_prep(const float* __restrict__ hs, const float* __restrict__ w,
                       const long long* __restrict__ labels) {
    int bx = blockIdx.x;
    if (bx < HQ_BLOCKS) {
        size_t idx = (size_t)bx * 256 + threadIdx.x;   // h quad index
        int n = (int)(idx >> 9);
        int d = (int)(idx & 511) * 4;
        float4 v = make_float4(0.f, 0.f, 0.f, 0.f);
        if (n < NROWS) {
            int b = n / (S_ - 1), s = n % (S_ - 1);
            v = *reinterpret_cast<const float4*>(hs + ((size_t)(b * S_ + s) * D_ + d));
        }
        int kit = d >> 6, c = d & 63;
        size_t tile = ((size_t)((n >> 7) * KITERS + kit)) << 13;
        uint32_t byte = (uint32_t)(n & 127) * 128u + (uint32_t)c * 2u;
        __half2* p = reinterpret_cast<__half2*>(
            reinterpret_cast<char*>(g_h + tile) + swz128(byte));
        p[0] = __floats2half2_rn(v.x, v.y);
        p[1] = __floats2half2_rn(v.z, v.w);
    } else if (bx < HQ_BLOCKS + WQ_BLOCKS) {
        size_t idx = (size_t)(bx - HQ_BLOCKS) * 256 + threadIdx.x;   // w quad index
        int v = (int)(idx >> 9);
        int d = (int)(idx & 511) * 4;
        float4 val = *reinterpret_cast<const float4*>(w + (size_t)v * D_ + d);
        int kit = d >> 6, c = d & 63;
        size_t tile = ((size_t)((v >> 7) * KITERS + kit)) << 13;
        uint32_t byte = (uint32_t)(v & 127) * 128u + (uint32_t)c * 2u;
        __half2* p = reinterpret_cast<__half2*>(
            reinterpret_cast<char*>(g_w + tile) + swz128(byte));
        p[0] = __floats2half2_rn(val.x, val.y);
        p[1] = __floats2half2_rn(val.z, val.w);
    } else {
        int n = (bx - HQ_BLOCKS - WQ_BLOCKS) * 256 + threadIdx.x;
        if (n < MPAD) {
            int v = -1;
            if (n < NROWS) {
                int b = n / (S_ - 1), s = n % (S_ - 1);
                long long t = labels[b * S_ + s + 1];
                v = (t != IGNORE_INDEX && t >= 0 && t < V_) ? (int)t : -1;
            }
            g_lab[n] = v;
        }
        if (n == 0) g_done = 0;   // reset reduce finalize ticket every call
    }
}

// ---- fused GEMM (mma.sync fp16) + partial logsumexp + gold extraction ----
// 256 threads, 2 CTAs/SM (best measured structure). No block-wide barriers
// in mainloop; deferred rotating-producer refill.
__global__ void __launch_bounds__(256, 2) k_gemm_lse() {
    extern __shared__ char smem_raw[];
    const uint32_t raw = smem_u32(smem_raw);
    const uint32_t sb = (raw + 1023u) & ~1023u;
    const uint32_t pad = sb - raw;
    float* s_redm = reinterpret_cast<float*>(smem_raw + pad + O_RED);         // [128][2]
    float* s_reds = reinterpret_cast<float*>(smem_raw + pad + O_RED + 1024);  // [128][2]
    const uint32_t o_full  = sb;        // 3 mbarriers (tx-based fills)
    const uint32_t o_empty = sb + 24;   // 3 mbarriers (count=256 consumer arrivals)
    const uint32_t o_stage = sb + O_STAGE;

    const int tid = threadIdx.x;
    const int wid = tid >> 5, l = tid & 31;
    const int mw = wid & 3, nw = wid >> 2;          // 4 M-warps x 2 N-warps
    const int wm = mw * 32, wn = nw * 64;

    if (tid == 0) {
        MBAR_INIT(o_full + 0, 1);   MBAR_INIT(o_full + 8, 1);   MBAR_INIT(o_full + 16, 1);
        MBAR_INIT(o_empty + 0, 256); MBAR_INIT(o_empty + 8, 256); MBAR_INIT(o_empty + 16, 256);
        FENCE_PROXY();
    }
    __syncthreads();

    const int mt = blockIdx.x, vc = blockIdx.y;
    const __half* ha = g_h + (size_t)mt * ((size_t)KITERS * A_ELEMS);
    const __half* wb = g_w + (size_t)vc * ((size_t)KITERS * B_ELEMS);

    if (tid == 0) {
        #pragma unroll
        for (int p = 0; p < NSTAGE; ++p) {
            MBAR_EXPECT_TX(o_full + 8 * p, STAGE_BYTES);
            BULK_G2S(o_stage + p * STAGE_BYTES,           ha + (size_t)p * A_ELEMS, A_BYTES, o_full + 8 * p);
            BULK_G2S(o_stage + p * STAGE_BYTES + A_BYTES, wb + (size_t)p * B_ELEMS, B_BYTES, o_full + 8 * p);
        }
    }

    // per-lane ldmatrix address components (swizzle mask depends only on row%8)
    const uint32_t a_row = (uint32_t)(wm + (l & 15));
    const uint32_t a_base = a_row * 128u;
    const uint32_t a_mask = (a_row & 7u) << 4;
    const uint32_t a_cb = (uint32_t)((l >> 4) * 16);
    const uint32_t b_row = (uint32_t)(wn + (l & 7) + ((l >> 4) << 3));
    const uint32_t b_base = b_row * 128u;
    const uint32_t b_mask = (b_row & 7u) << 4;
    const uint32_t b_cb = (uint32_t)(((l >> 3) & 1) * 16);

    float acc[2][8][4];
    #pragma unroll
    for (int i = 0; i < 2; ++i)
        #pragma unroll
        for (int j = 0; j < 8; ++j)
            #pragma unroll
            for (int q = 0; q < 4; ++q) acc[i][j][q] = 0.f;

    int s = 0, ph = 0;
    for (int it = 0; it < KITERS; ++it) {
        // Deferred refill: service the stage freed at iteration it-1.
        // Producer rotates: lane 0 of warp (it & 7).
        if (it >= 1 && it - 1 + NSTAGE < KITERS && tid == ((it & 7) << 5)) {
            const int sp = (it - 1) % NSTAGE;
            const uint32_t pA = o_stage + sp * STAGE_BYTES;
            MBAR_WAIT(o_empty + 8 * sp, ((it - 1) / NSTAGE) & 1);
            MBAR_EXPECT_TX(o_full + 8 * sp, STAGE_BYTES);
            BULK_G2S(pA,           ha + (size_t)(it - 1 + NSTAGE) * A_ELEMS, A_BYTES, o_full + 8 * sp);
            BULK_G2S(pA + A_BYTES, wb + (size_t)(it - 1 + NSTAGE) * B_ELEMS, B_BYTES, o_full + 8 * sp);
        }
        MBAR_WAIT(o_full + 8 * s, ph);
        const uint32_t stA = o_stage + s * STAGE_BYTES;
        const uint32_t stB = stA + A_BYTES;
        #pragma unroll
        for (int kk = 0; kk < 4; ++kk) {
            uint32_t a0[4], a1[4], b[4][4];
            const uint32_t aAdr = stA + a_base + ((a_cb + kk * 32u) ^ a_mask);
            LDSM_X4(a0[0], a0[1], a0[2], a0[3], aAdr);
            LDSM_X4(a1[0], a1[1], a1[2], a1[3], aAdr + 2048u);
            const uint32_t bAdr = stB + b_base + ((b_cb + kk * 32u) ^ b_mask);
            #pragma unroll
            for (int j = 0; j < 4; ++j)
                LDSM_X4(b[j][0], b[j][1], b[j][2], b[j][3], bAdr + (uint32_t)j * 2048u);
            #pragma unroll
            for (int j = 0; j < 4; ++j) {
                MMA16816(acc[0][2 * j],     a0[0], a0[1], a0[2], a0[3], b[j][0], b[j][1]);
                MMA16816(acc[1][2 * j],     a1[0], a1[1], a1[2], a1[3], b[j][0], b[j][1]);
                MMA16816(acc[0][2 * j + 1], a0[0], a0[1], a0[2], a0[3], b[j][2], b[j][3]);
                MMA16816(acc[1][2 * j + 1], a1[0], a1[1], a1[2], a1[3], b[j][2], b[j][3]);
            }
        }
        MBAR_ARRIVE(o_empty + 8 * s);   // release: my reads of stage s done
        if (++s == NSTAGE) { s = 0; ph ^= 1; }
    }

    // ---- gold extraction: if this tile's columns contain row's label, the
    //      owning thread writes the fp16-GEMM logit (consistent with lse) ----
    #pragma unroll
    for (int sl = 0; sl < 4; ++sl) {
        int row = wm + (sl >> 1) * 16 + (sl & 1) * 8 + (l >> 2);
        int t = g_lab[mt * 128 + row];
        int local = t - vc * NT - wn;
        if (local >= 0 && local < 64) {
            int mti = sl >> 1, h = sl & 1;
            #pragma unroll
            for (int j = 0; j < 8; ++j)
                #pragma unroll
                for (int c = 0; c < 2; ++c) {
                    int coln = (j >> 1) * 16 + (j & 1) * 8 + (l & 3) * 2 + c;
                    if (coln == local)
                        g_gold[mt * 128 + row] = acc[mti][j][2 * h + c];
                }
        }
    }

    // ---- epilogue: per-row max & sum(exp) over this CTA's 128 columns ----
    float mx[4];
    #pragma unroll
    for (int mti = 0; mti < 2; ++mti)
        #pragma unroll
        for (int h = 0; h < 2; ++h) {
            float m = -1e30f;
            #pragma unroll
            for (int j = 0; j < 8; ++j)
                m = fmaxf(m, fmaxf(acc[mti][j][2 * h], acc[mti][j][2 * h + 1]));
            m = fmaxf(m, __shfl_xor_sync(0xffffffffu, m, 1));
            m = fmaxf(m, __shfl_xor_sync(0xffffffffu, m, 2));
            mx[mti * 2 + h] = m;
        }
    if ((l & 3) == 0) {
        #pragma unroll
        for (int sl = 0; sl < 4; ++sl) {
            int row = wm + (sl >> 1) * 16 + (sl & 1) * 8 + (l >> 2);
            s_redm[row * 2 + nw] = mx[sl];
        }
    }
    __syncthreads();
    float fm[4], sm[4];
    #pragma unroll
    for (int sl = 0; sl < 4; ++sl) {
        int row = wm + (sl >> 1) * 16 + (sl & 1) * 8 + (l >> 2);
        float m = fmaxf(s_redm[row * 2 + 0], s_redm[row * 2 + 1]);
        fm[sl] = m;
        int mti = sl >> 1, h = sl & 1;
        float ss = 0.f;
        #pragma unroll
        for (int j = 0; j < 8; ++j)
            ss += __expf(acc[mti][j][2 * h] - m) + __expf(acc[mti][j][2 * h + 1] - m);
        ss += __shfl_xor_sync(0xffffffffu, ss, 1);
        ss += __shfl_xor_sync(0xffffffffu, ss, 2);
        sm[sl] = ss;
    }
    if ((l & 3) == 0) {
        #pragma unroll
        for (int sl = 0; sl < 4; ++sl) {
            int row = wm + (sl >> 1) * 16 + (sl & 1) * 8 + (l >> 2);
            s_reds[row * 2 + nw] = sm[sl];
        }
    }
    __syncthreads();
    if (nw == 0 && (l & 3) == 0) {
        #pragma unroll
        for (int sl = 0; sl < 4; ++sl) {
            int row = wm + (sl >> 1) * 16 + (sl & 1) * 8 + (l >> 2);
            float tot = s_reds[row * 2 + 0] + s_reds[row * 2 + 1];
            size_t g = (size_t)vc * MPAD + (size_t)mt * 128 + row;
            g_pmax[g] = fm[sl];
            g_psum[g] = tot;
        }
    }
}

// ---- combine split-lse partials; block sums + last-block finalize ----
__global__ void k_reduce(float* __restrict__ out) {
    __shared__ float s_nll[256], s_cnt[256];
    int row = blockIdx.x * 256 + threadIdx.x;
    float nll = 0.f, cnt = 0.f;
    if (row < NROWS) {
        int t = g_lab[row];
        if (t >= 0) {
            float m = -1e30f;
            for (int c = 0; c < VCHUNKS; ++c)
                m = fmaxf(m, g_pmax[(size_t)c * MPAD + row]);
            float ss = 0.f;
            for (int c = 0; c < VCHUNKS; ++c)
                ss += g_psum[(size_t)c * MPAD + row] *
                      __expf(g_pmax[(size_t)c * MPAD + row] - m);
            nll = m + __logf(ss) - g_gold[row];
            cnt = 1.f;
        }
    }
    s_nll[threadIdx.x] = nll; s_cnt[threadIdx.x] = cnt;
    __syncthreads();
    for (int o = 128; o; o >>= 1) {
        if (threadIdx.x < o) {
            s_nll[threadIdx.x] += s_nll[threadIdx.x + o];
            s_cnt[threadIdx.x] += s_cnt[threadIdx.x + o];
        }
        __syncthreads();
    }
    if (threadIdx.x == 0) {
        g_bsum[blockIdx.x] = s_nll[0];
        g_bcnt[blockIdx.x] = s_cnt[0];
        __threadfence();
        int t = atomicAdd(&g_done, 1);
        if (t == 31) {   // last block: deterministic fixed-order final sum
            float s = 0.f, c = 0.f;
            for (int i = 0; i < 32; ++i) { s += g_bsum[i]; c += g_bcnt[i]; }
            out[0] = s / fmaxf(c, 1.f);
        }
    }
}

extern "C" void kernel_launch(void* const* d_in, const int* in_sizes, int n_in,
                              void* d_out, int out_size) {
    const float* hs = (const float*)d_in[0];
    const float* w  = (const float*)d_in[1];
    const long long* labels = (const long long*)d_in[2];
    float* out = (float*)d_out;
    cudaFuncSetAttribute(k_gemm_lse, cudaFuncAttributeMaxDynamicSharedMemorySize, SMEM_REQ);
    k_prep<<<PREP_BLOCKS, 256>>>(hs, w, labels);
    dim3 grid(MTILES, VCHUNKS);
    k_gemm_lse<<<grid, 256, SMEM_REQ>>>();
    k_reduce<<<32, 256>>>(out);
}

// round 15
// speedup vs baseline: 3.4176x; 1.0078x over previous
#include <cuda_runtime.h>
#include <cuda_fp16.h>
#include <cstdint>

#define IGNORE_INDEX (-100)
static constexpr int B_ = 4, S_ = 2048, D_ = 2048, V_ = 32000;
static constexpr int NROWS  = B_ * (S_ - 1);   // 8188
static constexpr int MPAD   = 8192;
static constexpr int MTILES = MPAD / 128;      // 64
static constexpr int NT     = 128;             // CTA N tile / v-chunk
static constexpr int VCHUNKS = V_ / NT;        // 250
static constexpr int KC     = 64;              // K per stage
static constexpr int KITERS = D_ / KC;         // 32
static constexpr int A_ELEMS = 128 * KC;       // 8192
static constexpr int B_ELEMS = NT * KC;        // 8192
static constexpr int A_BYTES = A_ELEMS * 2;    // 16384
static constexpr int B_BYTES = B_ELEMS * 2;    // 16384
static constexpr int STAGE_BYTES = A_BYTES + B_BYTES;   // 32768
static constexpr int NSTAGE = 3;
// [0..48) mbarriers (3 full + 3 empty), [1024..2048) red-max, [2048..3072) red-sum
static constexpr int O_RED  = 1024;
static constexpr int O_STAGE = 3072;
static constexpr int SMEM_REQ = 1023 + O_STAGE + NSTAGE * STAGE_BYTES;  // 102399

// prep kernel grid sections (8 elems = one 16B store per thread)
static constexpr int HQ_BLOCKS  = (MPAD * (D_ / 8)) / 256;   // 8192
static constexpr int WQ_BLOCKS  = (V_ * (D_ / 8)) / 256;     // 32000
static constexpr int LAB_BLOCKS = MPAD / 256;                // 32
static constexpr int PREP_BLOCKS = HQ_BLOCKS + WQ_BLOCKS + LAB_BLOCKS;

__device__ __align__(1024) __half g_h[(size_t)MPAD * D_];
__device__ __align__(1024) __half g_w[(size_t)V_ * D_];
__device__ int   g_lab[MPAD];
__device__ float g_pmax[(size_t)VCHUNKS * MPAD];
__device__ float g_psum[(size_t)VCHUNKS * MPAD];
__device__ float g_gold[MPAD];
__device__ float g_bsum[32];
__device__ float g_bcnt[32];
__device__ int   g_done;

__device__ __forceinline__ uint32_t smem_u32(const void* p) {
    uint32_t a;
    asm("{ .reg .u64 t; cvta.to.shared.u64 t, %1; cvt.u32.u64 %0, t; }" : "=r"(a) : "l"(p));
    return a;
}
#define MBAR_INIT(a, c) \
    asm volatile("mbarrier.init.shared.b64 [%0], %1;" :: "r"(a), "r"(c) : "memory")
#define MBAR_EXPECT_TX(a, b) \
    asm volatile("mbarrier.arrive.expect_tx.shared.b64 _, [%0], %1;" :: "r"(a), "r"(b) : "memory")
#define MBAR_ARRIVE(a) \
    asm volatile("mbarrier.arrive.shared.b64 _, [%0];" :: "r"(a) : "memory")
#define MBAR_WAIT(mbar, ph) do {                                                        \
    uint32_t _m = (uint32_t)(mbar); uint32_t _p = (uint32_t)(ph); uint32_t _d;          \
    asm volatile("{\n\t.reg .pred p;\n\t"                                               \
        "mbarrier.try_wait.parity.acquire.cta.shared::cta.b64 p, [%1], %2;\n\t"         \
        "selp.b32 %0, 1, 0, p;\n\t}" : "=r"(_d) : "r"(_m), "r"(_p) : "memory");         \
    if (!_d) {                                                                          \
        asm volatile("{\n\t.reg .pred P1;\n"                                            \
            "WAIT_LOOP_%=:\n\t"                                                         \
            "mbarrier.try_wait.parity.acquire.cta.shared::cta.b64 P1, [%0], %1, 0x989680;\n\t" \
            "@P1 bra.uni WAIT_DONE_%=;\n\t"                                             \
            "bra.uni WAIT_LOOP_%=;\n"                                                   \
            "WAIT_DONE_%=:\n\t}" :: "r"(_m), "r"(_p) : "memory");                       \
    }                                                                                   \
} while (0)
#define BULK_G2S(dst, src, bytes, mbar)                                                 \
    asm volatile("cp.async.bulk.shared::cluster.global.mbarrier::complete_tx::bytes "   \
                 "[%0], [%1], %2, [%3];"                                                \
                 :: "r"(dst), "l"(src), "r"(bytes), "r"(mbar) : "memory")
#define FENCE_PROXY() asm volatile("fence.proxy.async.shared::cta;" ::: "memory")

#define LDSM_X4(r0, r1, r2, r3, addr) \
    asm volatile("ldmatrix.sync.aligned.m8n8.x4.shared.b16 {%0,%1,%2,%3}, [%4];" \
        : "=r"(r0), "=r"(r1), "=r"(r2), "=r"(r3) : "r"(addr))

#define MMA16816(d, a0, a1, a2, a3, b0, b1) \
    asm volatile("mma.sync.aligned.m16n8k16.row.col.f32.f16.f16.f32 " \
        "{%0,%1,%2,%3}, {%4,%5,%6,%7}, {%8,%9}, {%0,%1,%2,%3};" \
        : "+f"((d)[0]), "+f"((d)[1]), "+f"((d)[2]), "+f"((d)[3]) \
        : "r"(a0), "r"(a1), "r"(a2), "r"(a3), "r"(b0), "r"(b1))

__device__ __forceinline__ uint32_t swz128(uint32_t b) { return b ^ ((b >> 3) & 0x70); }

// pack 8 floats -> 8 fp16 in one uint4
__device__ __forceinline__ uint4 pack8(const float4& a, const float4& b) {
    uint4 r;
    __half2 h0 = __floats2half2_rn(a.x, a.y), h1 = __floats2half2_rn(a.z, a.w);
    __half2 h2 = __floats2half2_rn(b.x, b.y), h3 = __floats2half2_rn(b.z, b.w);
    r.x = *reinterpret_cast<uint32_t*>(&h0);
    r.y = *reinterpret_cast<uint32_t*>(&h1);
    r.z = *reinterpret_cast<uint32_t*>(&h2);
    r.w = *reinterpret_cast<uint32_t*>(&h3);
    return r;
}

// ---- fused prep: pack h (shifted) + pack W into tiled+swizzled fp16, and
//      build shifted labels + reset the reduce ticket. One launch.
//      8 elems/thread: two float4 loads, ONE 16B swizzled store (SW128 XORs
//      bits [6:4] so a 16B-aligned store stays 16B-aligned). ----
__global__ void k_prep(const float* __restrict__ hs, const float* __restrict__ w,
                       const long long* __restrict__ labels) {
    int bx = blockIdx.x;
    if (bx < HQ_BLOCKS) {
        size_t idx = (size_t)bx * 256 + threadIdx.x;   // h oct index
        int n = (int)(idx >> 8);                       // 256 octs per row
        int d = (int)(idx & 255) * 8;
        float4 v0 = make_float4(0.f, 0.f, 0.f, 0.f), v1 = v0;
        if (n < NROWS) {
            int b = n / (S_ - 1), s = n % (S_ - 1);
            const float* p = hs + ((size_t)(b * S_ + s) * D_ + d);
            v0 = *reinterpret_cast<const float4*>(p);
            v1 = *reinterpret_cast<const float4*>(p + 4);
        }
        int kit = d >> 6, c = d & 63;
        size_t tile = ((size_t)((n >> 7) * KITERS + kit)) << 13;
        uint32_t byte = (uint32_t)(n & 127) * 128u + (uint32_t)c * 2u;   // 16B-aligned
        *reinterpret_cast<uint4*>(
            reinterpret_cast<char*>(g_h + tile) + swz128(byte)) = pack8(v0, v1);
    } else if (bx < HQ_BLOCKS + WQ_BLOCKS) {
        size_t idx = (size_t)(bx - HQ_BLOCKS) * 256 + threadIdx.x;   // w oct index
        int v = (int)(idx >> 8);
        int d = (int)(idx & 255) * 8;
        const float* p = w + (size_t)v * D_ + d;
        float4 v0 = *reinterpret_cast<const float4*>(p);
        float4 v1 = *reinterpret_cast<const float4*>(p + 4);
        int kit = d >> 6, c = d & 63;
        size_t tile = ((size_t)((v >> 7) * KITERS + kit)) << 13;
        uint32_t byte = (uint32_t)(v & 127) * 128u + (uint32_t)c * 2u;
        *reinterpret_cast<uint4*>(
            reinterpret_cast<char*>(g_w + tile) + swz128(byte)) = pack8(v0, v1);
    } else {
        int n = (bx - HQ_BLOCKS - WQ_BLOCKS) * 256 + threadIdx.x;
        if (n < MPAD) {
            int v = -1;
            if (n < NROWS) {
                int b = n / (S_ - 1), s = n % (S_ - 1);
                long long t = labels[b * S_ + s + 1];
                v = (t != IGNORE_INDEX && t >= 0 && t < V_) ? (int)t : -1;
            }
            g_lab[n] = v;
        }
        if (n == 0) g_done = 0;   // reset reduce finalize ticket every call
    }
}

// ---- fused GEMM (mma.sync fp16) + partial logsumexp + gold extraction ----
// 256 threads, 2 CTAs/SM (best measured structure). No block-wide barriers
// in mainloop; deferred rotating-producer refill.
__global__ void __launch_bounds__(256, 2) k_gemm_lse() {
    extern __shared__ char smem_raw[];
    const uint32_t raw = smem_u32(smem_raw);
    const uint32_t sb = (raw + 1023u) & ~1023u;
    const uint32_t pad = sb - raw;
    float* s_redm = reinterpret_cast<float*>(smem_raw + pad + O_RED);         // [128][2]
    float* s_reds = reinterpret_cast<float*>(smem_raw + pad + O_RED + 1024);  // [128][2]
    const uint32_t o_full  = sb;        // 3 mbarriers (tx-based fills)
    const uint32_t o_empty = sb + 24;   // 3 mbarriers (count=256 consumer arrivals)
    const uint32_t o_stage = sb + O_STAGE;

    const int tid = threadIdx.x;
    const int wid = tid >> 5, l = tid & 31;
    const int mw = wid & 3, nw = wid >> 2;          // 4 M-warps x 2 N-warps
    const int wm = mw * 32, wn = nw * 64;

    if (tid == 0) {
        MBAR_INIT(o_full + 0, 1);   MBAR_INIT(o_full + 8, 1);   MBAR_INIT(o_full + 16, 1);
        MBAR_INIT(o_empty + 0, 256); MBAR_INIT(o_empty + 8, 256); MBAR_INIT(o_empty + 16, 256);
        FENCE_PROXY();
    }
    __syncthreads();

    const int mt = blockIdx.x, vc = blockIdx.y;
    const __half* ha = g_h + (size_t)mt * ((size_t)KITERS * A_ELEMS);
    const __half* wb = g_w + (size_t)vc * ((size_t)KITERS * B_ELEMS);

    if (tid == 0) {
        #pragma unroll
        for (int p = 0; p < NSTAGE; ++p) {
            MBAR_EXPECT_TX(o_full + 8 * p, STAGE_BYTES);
            BULK_G2S(o_stage + p * STAGE_BYTES,           ha + (size_t)p * A_ELEMS, A_BYTES, o_full + 8 * p);
            BULK_G2S(o_stage + p * STAGE_BYTES + A_BYTES, wb + (size_t)p * B_ELEMS, B_BYTES, o_full + 8 * p);
        }
    }

    // per-lane ldmatrix address components (swizzle mask depends only on row%8)
    const uint32_t a_row = (uint32_t)(wm + (l & 15));
    const uint32_t a_base = a_row * 128u;
    const uint32_t a_mask = (a_row & 7u) << 4;
    const uint32_t a_cb = (uint32_t)((l >> 4) * 16);
    const uint32_t b_row = (uint32_t)(wn + (l & 7) + ((l >> 4) << 3));
    const uint32_t b_base = b_row * 128u;
    const uint32_t b_mask = (b_row & 7u) << 4;
    const uint32_t b_cb = (uint32_t)(((l >> 3) & 1) * 16);

    float acc[2][8][4];
    #pragma unroll
    for (int i = 0; i < 2; ++i)
        #pragma unroll
        for (int j = 0; j < 8; ++j)
            #pragma unroll
            for (int q = 0; q < 4; ++q) acc[i][j][q] = 0.f;

    int s = 0, ph = 0;
    for (int it = 0; it < KITERS; ++it) {
        // Deferred refill: service the stage freed at iteration it-1.
        // Producer rotates: lane 0 of warp (it & 7).
        if (it >= 1 && it - 1 + NSTAGE < KITERS && tid == ((it & 7) << 5)) {
            const int sp = (it - 1) % NSTAGE;
            const uint32_t pA = o_stage + sp * STAGE_BYTES;
            MBAR_WAIT(o_empty + 8 * sp, ((it - 1) / NSTAGE) & 1);
            MBAR_EXPECT_TX(o_full + 8 * sp, STAGE_BYTES);
            BULK_G2S(pA,           ha + (size_t)(it - 1 + NSTAGE) * A_ELEMS, A_BYTES, o_full + 8 * sp);
            BULK_G2S(pA + A_BYTES, wb + (size_t)(it - 1 + NSTAGE) * B_ELEMS, B_BYTES, o_full + 8 * sp);
        }
        MBAR_WAIT(o_full + 8 * s, ph);
        const uint32_t stA = o_stage + s * STAGE_BYTES;
        const uint32_t stB = stA + A_BYTES;
        #pragma unroll
        for (int kk = 0; kk < 4; ++kk) {
            uint32_t a0[4], a1[4], b[4][4];
            const uint32_t aAdr = stA + a_base + ((a_cb + kk * 32u) ^ a_mask);
            LDSM_X4(a0[0], a0[1], a0[2], a0[3], aAdr);
            LDSM_X4(a1[0], a1[1], a1[2], a1[3], aAdr + 2048u);
            const uint32_t bAdr = stB + b_base + ((b_cb + kk * 32u) ^ b_mask);
            #pragma unroll
            for (int j = 0; j < 4; ++j)
                LDSM_X4(b[j][0], b[j][1], b[j][2], b[j][3], bAdr + (uint32_t)j * 2048u);
            #pragma unroll
            for (int j = 0; j < 4; ++j) {
                MMA16816(acc[0][2 * j],     a0[0], a0[1], a0[2], a0[3], b[j][0], b[j][1]);
                MMA16816(acc[1][2 * j],     a1[0], a1[1], a1[2], a1[3], b[j][0], b[j][1]);
                MMA16816(acc[0][2 * j + 1], a0[0], a0[1], a0[2], a0[3], b[j][2], b[j][3]);
                MMA16816(acc[1][2 * j + 1], a1[0], a1[1], a1[2], a1[3], b[j][2], b[j][3]);
            }
        }
        MBAR_ARRIVE(o_empty + 8 * s);   // release: my reads of stage s done
        if (++s == NSTAGE) { s = 0; ph ^= 1; }
    }

    // ---- gold extraction: if this tile's columns contain row's label, the
    //      owning thread writes the fp16-GEMM logit (consistent with lse) ----
    #pragma unroll
    for (int sl = 0; sl < 4; ++sl) {
        int row = wm + (sl >> 1) * 16 + (sl & 1) * 8 + (l >> 2);
        int t = g_lab[mt * 128 + row];
        int local = t - vc * NT - wn;
        if (local >= 0 && local < 64) {
            int mti = sl >> 1, h = sl & 1;
            #pragma unroll
            for (int j = 0; j < 8; ++j)
                #pragma unroll
                for (int c = 0; c < 2; ++c) {
                    int coln = (j >> 1) * 16 + (j & 1) * 8 + (l & 3) * 2 + c;
                    if (coln == local)
                        g_gold[mt * 128 + row] = acc[mti][j][2 * h + c];
                }
        }
    }

    // ---- epilogue: per-row max & sum(exp) over this CTA's 128 columns ----
    float mx[4];
    #pragma unroll
    for (int mti = 0; mti < 2; ++mti)
        #pragma unroll
        for (int h = 0; h < 2; ++h) {
            float m = -1e30f;
            #pragma unroll
            for (int j = 0; j < 8; ++j)
                m = fmaxf(m, fmaxf(acc[mti][j][2 * h], acc[mti][j][2 * h + 1]));
            m = fmaxf(m, __shfl_xor_sync(0xffffffffu, m, 1));
            m = fmaxf(m, __shfl_xor_sync(0xffffffffu, m, 2));
            mx[mti * 2 + h] = m;
        }
    if ((l & 3) == 0) {
        #pragma unroll
        for (int sl = 0; sl < 4; ++sl) {
            int row = wm + (sl >> 1) * 16 + (sl & 1) * 8 + (l >> 2);
            s_redm[row * 2 + nw] = mx[sl];
        }
    }
    __syncthreads();
    float fm[4], sm[4];
    #pragma unroll
    for (int sl = 0; sl < 4; ++sl) {
        int row = wm + (sl >> 1) * 16 + (sl & 1) * 8 + (l >> 2);
        float m = fmaxf(s_redm[row * 2 + 0], s_redm[row * 2 + 1]);
        fm[sl] = m;
        int mti = sl >> 1, h = sl & 1;
        float ss = 0.f;
        #pragma unroll
        for (int j = 0; j < 8; ++j)
            ss += __expf(acc[mti][j][2 * h] - m) + __expf(acc[mti][j][2 * h + 1] - m);
        ss += __shfl_xor_sync(0xffffffffu, ss, 1);
        ss += __shfl_xor_sync(0xffffffffu, ss, 2);
        sm[sl] = ss;
    }
    if ((l & 3) == 0) {
        #pragma unroll
        for (int sl = 0; sl < 4; ++sl) {
            int row = wm + (sl >> 1) * 16 + (sl & 1) * 8 + (l >> 2);
            s_reds[row * 2 + nw] = sm[sl];
        }
    }
    __syncthreads();
    if (nw == 0 && (l & 3) == 0) {
        #pragma unroll
        for (int sl = 0; sl < 4; ++sl) {
            int row = wm + (sl >> 1) * 16 + (sl & 1) * 8 + (l >> 2);
            float tot = s_reds[row * 2 + 0] + s_reds[row * 2 + 1];
            size_t g = (size_t)vc * MPAD + (size_t)mt * 128 + row;
            g_pmax[g] = fm[sl];
            g_psum[g] = tot;
        }
    }
}

// ---- combine split-lse partials; block sums + last-block finalize ----
__global__ void k_reduce(float* __restrict__ out) {
    __shared__ float s_nll[256], s_cnt[256];
    int row = blockIdx.x * 256 + threadIdx.x;
    float nll = 0.f, cnt = 0.f;
    if (row < NROWS) {
        int t = g_lab[row];
        if (t >= 0) {
            float m = -1e30f;
            for (int c = 0; c < VCHUNKS; ++c)
                m = fmaxf(m, g_pmax[(size_t)c * MPAD + row]);
            float ss = 0.f;
            for (int c = 0; c < VCHUNKS; ++c)
                ss += g_psum[(size_t)c * MPAD + row] *
                      __expf(g_pmax[(size_t)c * MPAD + row] - m);
            nll = m + __logf(ss) - g_gold[row];
            cnt = 1.f;
        }
    }
    s_nll[threadIdx.x] = nll; s_cnt[threadIdx.x] = cnt;
    __syncthreads();
    for (int o = 128; o; o >>= 1) {
        if (threadIdx.x < o) {
            s_nll[threadIdx.x] += s_nll[threadIdx.x + o];
            s_cnt[threadIdx.x] += s_cnt[threadIdx.x + o];
        }
        __syncthreads();
    }
    if (threadIdx.x == 0) {
        g_bsum[blockIdx.x] = s_nll[0];
        g_bcnt[blockIdx.x] = s_cnt[0];
        __threadfence();
        int t = atomicAdd(&g_done, 1);
        if (t == 31) {   // last block: deterministic fixed-order final sum
            float s = 0.f, c = 0.f;
            for (int i = 0; i < 32; ++i) { s += g_bsum[i]; c += g_bcnt[i]; }
            out[0] = s / fmaxf(c, 1.f);
        }
    }
}

extern "C" void kernel_launch(void* const* d_in, const int* in_sizes, int n_in,
                              void* d_out, int out_size) {
    const float* hs = (const float*)d_in[0];
    const float* w  = (const float*)d_in[1];
    const long long* labels = (const long long*)d_in[2];
    float* out = (float*)d_out;
    cudaFuncSetAttribute(k_gemm_lse, cudaFuncAttributeMaxDynamicSharedMemorySize, SMEM_REQ);
    k_prep<<<PREP_BLOCKS, 256>>>(hs, w, labels);
    dim3 grid(MTILES, VCHUNKS);
    k_gemm_lse<<<grid, 256, SMEM_REQ>>>();
    k_reduce<<<32, 256>>>(out);
}

// round 16
// speedup vs baseline: 3.4370x; 1.0057x over previous
#include <cuda_runtime.h>
#include <cuda_fp16.h>
#include <cstdint>

#define IGNORE_INDEX (-100)
static constexpr int B_ = 4, S_ = 2048, D_ = 2048, V_ = 32000;
static constexpr int NROWS  = B_ * (S_ - 1);   // 8188
static constexpr int MPAD   = 8192;
static constexpr int MTILES = MPAD / 128;      // 64
static constexpr int NT     = 128;             // CTA N tile / v-chunk
static constexpr int VCHUNKS = V_ / NT;        // 250
static constexpr int KC     = 64;              // K per stage
static constexpr int KITERS = D_ / KC;         // 32
static constexpr int A_ELEMS = 128 * KC;       // 8192
static constexpr int B_ELEMS = NT * KC;        // 8192
static constexpr int A_BYTES = A_ELEMS * 2;    // 16384
static constexpr int B_BYTES = B_ELEMS * 2;    // 16384
static constexpr int STAGE_BYTES = A_BYTES + B_BYTES;   // 32768
static constexpr int NSTAGE = 3;
// [0..48) mbarriers (3 full + 3 empty), [1024..2048) red-max, [2048..3072) red-sum
static constexpr int O_RED  = 1024;
static constexpr int O_STAGE = 3072;
static constexpr int SMEM_REQ = 1023 + O_STAGE + NSTAGE * STAGE_BYTES;  // 102399

// prep kernel grid sections (16 elems = two 16B stores per thread)
static constexpr int HQ_BLOCKS  = (MPAD * (D_ / 16)) / 256;  // 4096
static constexpr int WQ_BLOCKS  = (V_ * (D_ / 16)) / 256;    // 16000
static constexpr int LAB_BLOCKS = MPAD / 256;                // 32
static constexpr int PREP_BLOCKS = HQ_BLOCKS + WQ_BLOCKS + LAB_BLOCKS;

__device__ __align__(1024) __half g_h[(size_t)MPAD * D_];
__device__ __align__(1024) __half g_w[(size_t)V_ * D_];
__device__ int   g_lab[MPAD];
__device__ float g_plse[(size_t)VCHUNKS * MPAD];   // fused per-chunk partial lse
__device__ float g_gold[MPAD];
__device__ float g_bsum[32];
__device__ float g_bcnt[32];
__device__ int   g_done;

__device__ __forceinline__ uint32_t smem_u32(const void* p) {
    uint32_t a;
    asm("{ .reg .u64 t; cvta.to.shared.u64 t, %1; cvt.u32.u64 %0, t; }" : "=r"(a) : "l"(p));
    return a;
}
#define MBAR_INIT(a, c) \
    asm volatile("mbarrier.init.shared.b64 [%0], %1;" :: "r"(a), "r"(c) : "memory")
#define MBAR_EXPECT_TX(a, b) \
    asm volatile("mbarrier.arrive.expect_tx.shared.b64 _, [%0], %1;" :: "r"(a), "r"(b) : "memory")
#define MBAR_ARRIVE(a) \
    asm volatile("mbarrier.arrive.shared.b64 _, [%0];" :: "r"(a) : "memory")
#define MBAR_WAIT(mbar, ph) do {                                                        \
    uint32_t _m = (uint32_t)(mbar); uint32_t _p = (uint32_t)(ph); uint32_t _d;          \
    asm volatile("{\n\t.reg .pred p;\n\t"                                               \
        "mbarrier.try_wait.parity.acquire.cta.shared::cta.b64 p, [%1], %2;\n\t"         \
        "selp.b32 %0, 1, 0, p;\n\t}" : "=r"(_d) : "r"(_m), "r"(_p) : "memory");         \
    if (!_d) {                                                                          \
        asm volatile("{\n\t.reg .pred P1;\n"                                            \
            "WAIT_LOOP_%=:\n\t"                                                         \
            "mbarrier.try_wait.parity.acquire.cta.shared::cta.b64 P1, [%0], %1, 0x989680;\n\t" \
            "@P1 bra.uni WAIT_DONE_%=;\n\t"                                             \
            "bra.uni WAIT_LOOP_%=;\n"                                                   \
            "WAIT_DONE_%=:\n\t}" :: "r"(_m), "r"(_p) : "memory");                       \
    }                                                                                   \
} while (0)
#define BULK_G2S(dst, src, bytes, mbar)                                                 \
    asm volatile("cp.async.bulk.shared::cluster.global.mbarrier::complete_tx::bytes "   \
                 "[%0], [%1], %2, [%3];"                                                \
                 :: "r"(dst), "l"(src), "r"(bytes), "r"(mbar) : "memory")
#define FENCE_PROXY() asm volatile("fence.proxy.async.shared::cta;" ::: "memory")

#define LDSM_X4(r0, r1, r2, r3, addr) \
    asm volatile("ldmatrix.sync.aligned.m8n8.x4.shared.b16 {%0,%1,%2,%3}, [%4];" \
        : "=r"(r0), "=r"(r1), "=r"(r2), "=r"(r3) : "r"(addr))

#define MMA16816(d, a0, a1, a2, a3, b0, b1) \
    asm volatile("mma.sync.aligned.m16n8k16.row.col.f32.f16.f16.f32 " \
        "{%0,%1,%2,%3}, {%4,%5,%6,%7}, {%8,%9}, {%0,%1,%2,%3};" \
        : "+f"((d)[0]), "+f"((d)[1]), "+f"((d)[2]), "+f"((d)[3]) \
        : "r"(a0), "r"(a1), "r"(a2), "r"(a3), "r"(b0), "r"(b1))

__device__ __forceinline__ uint32_t swz128(uint32_t b) { return b ^ ((b >> 3) & 0x70); }

// pack 8 floats -> 8 fp16 in one uint4
__device__ __forceinline__ uint4 pack8(const float4& a, const float4& b) {
    uint4 r;
    __half2 h0 = __floats2half2_rn(a.x, a.y), h1 = __floats2half2_rn(a.z, a.w);
    __half2 h2 = __floats2half2_rn(b.x, b.y), h3 = __floats2half2_rn(b.z, b.w);
    r.x = *reinterpret_cast<uint32_t*>(&h0);
    r.y = *reinterpret_cast<uint32_t*>(&h1);
    r.z = *reinterpret_cast<uint32_t*>(&h2);
    r.w = *reinterpret_cast<uint32_t*>(&h3);
    return r;
}

// ---- fused prep: pack h (shifted) + pack W into tiled+swizzled fp16, and
//      build shifted labels + reset the reduce ticket. One launch.
//      16 elems/thread: four float4 loads, two independently-swizzled 16B
//      stores (the +16 carry can change swizzle bits >= 7, so two swz calls). ----
__global__ void k_prep(const float* __restrict__ hs, const float* __restrict__ w,
                       const long long* __restrict__ labels) {
    int bx = blockIdx.x;
    if (bx < HQ_BLOCKS) {
        size_t idx = (size_t)bx * 256 + threadIdx.x;   // h 16-elem index
        int n = (int)(idx >> 7);                       // 128 per row
        int d = (int)(idx & 127) * 16;
        float4 v0 = make_float4(0.f, 0.f, 0.f, 0.f), v1 = v0, v2 = v0, v3 = v0;
        if (n < NROWS) {
            int b = n / (S_ - 1), s = n % (S_ - 1);
            const float* p = hs + ((size_t)(b * S_ + s) * D_ + d);
            v0 = *reinterpret_cast<const float4*>(p);
            v1 = *reinterpret_cast<const float4*>(p + 4);
            v2 = *reinterpret_cast<const float4*>(p + 8);
            v3 = *reinterpret_cast<const float4*>(p + 12);
        }
        int kit = d >> 6, c = d & 63;
        size_t tile = ((size_t)((n >> 7) * KITERS + kit)) << 13;
        char* tb = reinterpret_cast<char*>(g_h + tile);
        uint32_t byte = (uint32_t)(n & 127) * 128u + (uint32_t)c * 2u;   // 16B-aligned
        *reinterpret_cast<uint4*>(tb + swz128(byte))      = pack8(v0, v1);
        *reinterpret_cast<uint4*>(tb + swz128(byte + 16)) = pack8(v2, v3);
    } else if (bx < HQ_BLOCKS + WQ_BLOCKS) {
        size_t idx = (size_t)(bx - HQ_BLOCKS) * 256 + threadIdx.x;   // w 16-elem index
        int v = (int)(idx >> 7);
        int d = (int)(idx & 127) * 16;
        const float* p = w + (size_t)v * D_ + d;
        float4 v0 = *reinterpret_cast<const float4*>(p);
        float4 v1 = *reinterpret_cast<const float4*>(p + 4);
        float4 v2 = *reinterpret_cast<const float4*>(p + 8);
        float4 v3 = *reinterpret_cast<const float4*>(p + 12);
        int kit = d >> 6, c = d & 63;
        size_t tile = ((size_t)((v >> 7) * KITERS + kit)) << 13;
        char* tb = reinterpret_cast<char*>(g_w + tile);
        uint32_t byte = (uint32_t)(v & 127) * 128u + (uint32_t)c * 2u;
        *reinterpret_cast<uint4*>(tb + swz128(byte))      = pack8(v0, v1);
        *reinterpret_cast<uint4*>(tb + swz128(byte + 16)) = pack8(v2, v3);
    } else {
        int n = (bx - HQ_BLOCKS - WQ_BLOCKS) * 256 + threadIdx.x;
        if (n < MPAD) {
            int v = -1;
            if (n < NROWS) {
                int b = n / (S_ - 1), s = n % (S_ - 1);
                long long t = labels[b * S_ + s + 1];
                v = (t != IGNORE_INDEX && t >= 0 && t < V_) ? (int)t : -1;
            }
            g_lab[n] = v;
        }
        if (n == 0) g_done = 0;   // reset reduce finalize ticket every call
    }
}

// ---- fused GEMM (mma.sync fp16) + partial logsumexp + gold extraction ----
// 256 threads, 2 CTAs/SM (best measured structure). No block-wide barriers
// in mainloop; deferred rotating-producer refill. Epilogue now writes ONE
// fused partial per (row, chunk): plse = m + log(sum exp).
__global__ void __launch_bounds__(256, 2) k_gemm_lse() {
    extern __shared__ char smem_raw[];
    const uint32_t raw = smem_u32(smem_raw);
    const uint32_t sb = (raw + 1023u) & ~1023u;
    const uint32_t pad = sb - raw;
    float* s_redm = reinterpret_cast<float*>(smem_raw + pad + O_RED);         // [128][2]
    float* s_reds = reinterpret_cast<float*>(smem_raw + pad + O_RED + 1024);  // [128][2]
    const uint32_t o_full  = sb;        // 3 mbarriers (tx-based fills)
    const uint32_t o_empty = sb + 24;   // 3 mbarriers (count=256 consumer arrivals)
    const uint32_t o_stage = sb + O_STAGE;

    const int tid = threadIdx.x;
    const int wid = tid >> 5, l = tid & 31;
    const int mw = wid & 3, nw = wid >> 2;          // 4 M-warps x 2 N-warps
    const int wm = mw * 32, wn = nw * 64;

    if (tid == 0) {
        MBAR_INIT(o_full + 0, 1);   MBAR_INIT(o_full + 8, 1);   MBAR_INIT(o_full + 16, 1);
        MBAR_INIT(o_empty + 0, 256); MBAR_INIT(o_empty + 8, 256); MBAR_INIT(o_empty + 16, 256);
        FENCE_PROXY();
    }
    __syncthreads();

    const int mt = blockIdx.x, vc = blockIdx.y;
    const __half* ha = g_h + (size_t)mt * ((size_t)KITERS * A_ELEMS);
    const __half* wb = g_w + (size_t)vc * ((size_t)KITERS * B_ELEMS);

    if (tid == 0) {
        #pragma unroll
        for (int p = 0; p < NSTAGE; ++p) {
            MBAR_EXPECT_TX(o_full + 8 * p, STAGE_BYTES);
            BULK_G2S(o_stage + p * STAGE_BYTES,           ha + (size_t)p * A_ELEMS, A_BYTES, o_full + 8 * p);
            BULK_G2S(o_stage + p * STAGE_BYTES + A_BYTES, wb + (size_t)p * B_ELEMS, B_BYTES, o_full + 8 * p);
        }
    }

    // per-lane ldmatrix address components (swizzle mask depends only on row%8)
    const uint32_t a_row = (uint32_t)(wm + (l & 15));
    const uint32_t a_base = a_row * 128u;
    const uint32_t a_mask = (a_row & 7u) << 4;
    const uint32_t a_cb = (uint32_t)((l >> 4) * 16);
    const uint32_t b_row = (uint32_t)(wn + (l & 7) + ((l >> 4) << 3));
    const uint32_t b_base = b_row * 128u;
    const uint32_t b_mask = (b_row & 7u) << 4;
    const uint32_t b_cb = (uint32_t)(((l >> 3) & 1) * 16);

    float acc[2][8][4];
    #pragma unroll
    for (int i = 0; i < 2; ++i)
        #pragma unroll
        for (int j = 0; j < 8; ++j)
            #pragma unroll
            for (int q = 0; q < 4; ++q) acc[i][j][q] = 0.f;

    int s = 0, ph = 0;
    for (int it = 0; it < KITERS; ++it) {
        // Deferred refill: service the stage freed at iteration it-1.
        // Producer rotates: lane 0 of warp (it & 7).
        if (it >= 1 && it - 1 + NSTAGE < KITERS && tid == ((it & 7) << 5)) {
            const int sp = (it - 1) % NSTAGE;
            const uint32_t pA = o_stage + sp * STAGE_BYTES;
            MBAR_WAIT(o_empty + 8 * sp, ((it - 1) / NSTAGE) & 1);
            MBAR_EXPECT_TX(o_full + 8 * sp, STAGE_BYTES);
            BULK_G2S(pA,           ha + (size_t)(it - 1 + NSTAGE) * A_ELEMS, A_BYTES, o_full + 8 * sp);
            BULK_G2S(pA + A_BYTES, wb + (size_t)(it - 1 + NSTAGE) * B_ELEMS, B_BYTES, o_full + 8 * sp);
        }
        MBAR_WAIT(o_full + 8 * s, ph);
        const uint32_t stA = o_stage + s * STAGE_BYTES;
        const uint32_t stB = stA + A_BYTES;
        #pragma unroll
        for (int kk = 0; kk < 4; ++kk) {
            uint32_t a0[4], a1[4], b[4][4];
            const uint32_t aAdr = stA + a_base + ((a_cb + kk * 32u) ^ a_mask);
            LDSM_X4(a0[0], a0[1], a0[2], a0[3], aAdr);
            LDSM_X4(a1[0], a1[1], a1[2], a1[3], aAdr + 2048u);
            const uint32_t bAdr = stB + b_base + ((b_cb + kk * 32u) ^ b_mask);
            #pragma unroll
            for (int j = 0; j < 4; ++j)
                LDSM_X4(b[j][0], b[j][1], b[j][2], b[j][3], bAdr + (uint32_t)j * 2048u);
            #pragma unroll
            for (int j = 0; j < 4; ++j) {
                MMA16816(acc[0][2 * j],     a0[0], a0[1], a0[2], a0[3], b[j][0], b[j][1]);
                MMA16816(acc[1][2 * j],     a1[0], a1[1], a1[2], a1[3], b[j][0], b[j][1]);
                MMA16816(acc[0][2 * j + 1], a0[0], a0[1], a0[2], a0[3], b[j][2], b[j][3]);
                MMA16816(acc[1][2 * j + 1], a1[0], a1[1], a1[2], a1[3], b[j][2], b[j][3]);
            }
        }
        MBAR_ARRIVE(o_empty + 8 * s);   // release: my reads of stage s done
        if (++s == NSTAGE) { s = 0; ph ^= 1; }
    }

    // ---- gold extraction: if this tile's columns contain row's label, the
    //      owning thread writes the fp16-GEMM logit (consistent with lse) ----
    #pragma unroll
    for (int sl = 0; sl < 4; ++sl) {
        int row = wm + (sl >> 1) * 16 + (sl & 1) * 8 + (l >> 2);
        int t = g_lab[mt * 128 + row];
        int local = t - vc * NT - wn;
        if (local >= 0 && local < 64) {
            int mti = sl >> 1, h = sl & 1;
            #pragma unroll
            for (int j = 0; j < 8; ++j)
                #pragma unroll
                for (int c = 0; c < 2; ++c) {
                    int coln = (j >> 1) * 16 + (j & 1) * 8 + (l & 3) * 2 + c;
                    if (coln == local)
                        g_gold[mt * 128 + row] = acc[mti][j][2 * h + c];
                }
        }
    }

    // ---- epilogue: per-row max & sum(exp) over this CTA's 128 columns ----
    float mx[4];
    #pragma unroll
    for (int mti = 0; mti < 2; ++mti)
        #pragma unroll
        for (int h = 0; h < 2; ++h) {
            float m = -1e30f;
            #pragma unroll
            for (int j = 0; j < 8; ++j)
                m = fmaxf(m, fmaxf(acc[mti][j][2 * h], acc[mti][j][2 * h + 1]));
            m = fmaxf(m, __shfl_xor_sync(0xffffffffu, m, 1));
            m = fmaxf(m, __shfl_xor_sync(0xffffffffu, m, 2));
            mx[mti * 2 + h] = m;
        }
    if ((l & 3) == 0) {
        #pragma unroll
        for (int sl = 0; sl < 4; ++sl) {
            int row = wm + (sl >> 1) * 16 + (sl & 1) * 8 + (l >> 2);
            s_redm[row * 2 + nw] = mx[sl];
        }
    }
    __syncthreads();
    float fm[4], sm[4];
    #pragma unroll
    for (int sl = 0; sl < 4; ++sl) {
        int row = wm + (sl >> 1) * 16 + (sl & 1) * 8 + (l >> 2);
        float m = fmaxf(s_redm[row * 2 + 0], s_redm[row * 2 + 1]);
        fm[sl] = m;
        int mti = sl >> 1, h = sl & 1;
        float ss = 0.f;
        #pragma unroll
        for (int j = 0; j < 8; ++j)
            ss += __expf(acc[mti][j][2 * h] - m) + __expf(acc[mti][j][2 * h + 1] - m);
        ss += __shfl_xor_sync(0xffffffffu, ss, 1);
        ss += __shfl_xor_sync(0xffffffffu, ss, 2);
        sm[sl] = ss;
    }
    if ((l & 3) == 0) {
        #pragma unroll
        for (int sl = 0; sl < 4; ++sl) {
            int row = wm + (sl >> 1) * 16 + (sl & 1) * 8 + (l >> 2);
            s_reds[row * 2 + nw] = sm[sl];
        }
    }
    __syncthreads();
    if (nw == 0 && (l & 3) == 0) {
        #pragma unroll
        for (int sl = 0; sl < 4; ++sl) {
            int row = wm + (sl >> 1) * 16 + (sl & 1) * 8 + (l >> 2);
            float tot = s_reds[row * 2 + 0] + s_reds[row * 2 + 1];
            size_t g = (size_t)vc * MPAD + (size_t)mt * 128 + row;
            g_plse[g] = fm[sl] + __logf(tot);   // fused partial lse
        }
    }
}

// ---- combine fused partials; block sums + last-block finalize ----
__global__ void k_reduce(float* __restrict__ out) {
    __shared__ float s_nll[256], s_cnt[256];
    int row = blockIdx.x * 256 + threadIdx.x;
    float nll = 0.f, cnt = 0.f;
    if (row < NROWS) {
        int t = g_lab[row];
        if (t >= 0) {
            float m = -1e30f;
            for (int c = 0; c < VCHUNKS; ++c)
                m = fmaxf(m, g_plse[(size_t)c * MPAD + row]);
            float ss = 0.f;
            for (int c = 0; c < VCHUNKS; ++c)
                ss += __expf(g_plse[(size_t)c * MPAD + row] - m);
            nll = m + __logf(ss) - g_gold[row];
            cnt = 1.f;
        }
    }
    s_nll[threadIdx.x] = nll; s_cnt[threadIdx.x] = cnt;
    __syncthreads();
    for (int o = 128; o; o >>= 1) {
        if (threadIdx.x < o) {
            s_nll[threadIdx.x] += s_nll[threadIdx.x + o];
            s_cnt[threadIdx.x] += s_cnt[threadIdx.x + o];
        }
        __syncthreads();
    }
    if (threadIdx.x == 0) {
        g_bsum[blockIdx.x] = s_nll[0];
        g_bcnt[blockIdx.x] = s_cnt[0];
        __threadfence();
        int t = atomicAdd(&g_done, 1);
        if (t == 31) {   // last block: deterministic fixed-order final sum
            float s = 0.f, c = 0.f;
            for (int i = 0; i < 32; ++i) { s += g_bsum[i]; c += g_bcnt[i]; }
            out[0] = s / fmaxf(c, 1.f);
        }
    }
}

extern "C" void kernel_launch(void* const* d_in, const int* in_sizes, int n_in,
                              void* d_out, int out_size) {
    const float* hs = (const float*)d_in[0];
    const float* w  = (const float*)d_in[1];
    const long long* labels = (const long long*)d_in[2];
    float* out = (float*)d_out;
    cudaFuncSetAttribute(k_gemm_lse, cudaFuncAttributeMaxDynamicSharedMemorySize, SMEM_REQ);
    k_prep<<<PREP_BLOCKS, 256>>>(hs, w, labels);
    dim3 grid(MTILES, VCHUNKS);
    k_gemm_lse<<<grid, 256, SMEM_REQ>>>();
    k_reduce<<<32, 256>>>(out);
}